// round 9
// baseline (speedup 1.0000x reference)
#include <cuda_runtime.h>

#define NT 8192
#define ND 2048
#define NE 16
#define CAP 512
#define FULLM 0xFFFFFFFFu
#define CINF 0x7FFFFFFF

typedef unsigned long long u64;

__device__ float g_probsT[NE * NT];  // softmax probs, transposed [e][t]
__device__ u64   g_prefs[NT];        // packed expert-preference order (16 nibbles)

__device__ __forceinline__ u64 ffma2(u64 a, u64 b, u64 c) {
    u64 d;
    asm("fma.rn.f32x2 %0, %1, %2, %3;" : "=l"(d) : "l"(a), "l"(b), "l"(c));
    return d;
}

// =====================================================================
// Kernel 1: GEMV + fully parallel epilogue (softmax + rank-sort prefs)
// =====================================================================
__global__ void __launch_bounds__(128, 3) gemv_kernel(const float* __restrict__ f,
                                                      const float* __restrict__ W,
                                                      const float* __restrict__ b) {
    const int lane = threadIdx.x & 31;
    const int wid  = threadIdx.x >> 5;
    const int t0   = (blockIdx.x * 4 + wid) * 4;

    const ulonglong2* F  = reinterpret_cast<const ulonglong2*>(f + (size_t)t0 * ND);
    const ulonglong2* Wv = reinterpret_cast<const ulonglong2*>(W);

    u64 acc[4][NE];
#pragma unroll
    for (int t = 0; t < 4; ++t)
#pragma unroll
        for (int e = 0; e < NE; ++e) acc[t][e] = 0ull;

#pragma unroll 2
    for (int i = 0; i < 16; ++i) {
        const int k = i * 32 + lane;
        const ulonglong2 a0 = F[k];
        const ulonglong2 a1 = F[k + 512];
        const ulonglong2 a2 = F[k + 1024];
        const ulonglong2 a3 = F[k + 1536];
#pragma unroll
        for (int e = 0; e < NE; ++e) {
            const ulonglong2 w = Wv[e * 512 + k];
            acc[0][e] = ffma2(a0.x, w.x, acc[0][e]);
            acc[0][e] = ffma2(a0.y, w.y, acc[0][e]);
            acc[1][e] = ffma2(a1.x, w.x, acc[1][e]);
            acc[1][e] = ffma2(a1.y, w.y, acc[1][e]);
            acc[2][e] = ffma2(a2.x, w.x, acc[2][e]);
            acc[2][e] = ffma2(a2.y, w.y, acc[2][e]);
            acc[3][e] = ffma2(a3.x, w.x, acc[3][e]);
            acc[3][e] = ffma2(a3.y, w.y, acc[3][e]);
        }
    }

    // reduce; lane (t = lane>>4 [+2], e = lane&15) keeps its two values
    const int myE = lane & 15;
    const int myT = lane >> 4;
    float v0 = 0.f, v1 = 0.f;
#pragma unroll
    for (int t = 0; t < 4; ++t) {
#pragma unroll
        for (int e = 0; e < NE; ++e) {
            float sv = __uint_as_float((unsigned)acc[t][e]) +
                       __uint_as_float((unsigned)(acc[t][e] >> 32));
#pragma unroll
            for (int o = 16; o; o >>= 1) sv += __shfl_xor_sync(FULLM, sv, o);
            if (e == myE) {
                if (t == myT)     v0 = sv;
                if (t == myT + 2) v1 = sv;
            }
        }
    }

    const float bias = __ldg(b + myE);
#pragma unroll
    for (int p = 0; p < 2; ++p) {
        const int t = t0 + myT + 2 * p;
        const float a = (p ? v1 : v0) + bias;

        // softmax over the 16-lane group
        float m = a;
#pragma unroll
        for (int o = 1; o < 16; o <<= 1) m = fmaxf(m, __shfl_xor_sync(FULLM, m, o));
        const float ex = __expf(a - m);
        float s = ex;
#pragma unroll
        for (int o = 1; o < 16; o <<= 1) s += __shfl_xor_sync(FULLM, s, o);
        g_probsT[myE * NT + t] = __fdividef(ex, s);

        // sortable key + rank (descending score, tie -> lower expert first)
        unsigned u = __float_as_uint(a);
        u = (u & 0x80000000u) ? ~u : (u | 0x80000000u);
        int rank = 0;
#pragma unroll
        for (int k = 1; k < 16; ++k) {
            const unsigned ou = __shfl_xor_sync(FULLM, u, k);
            const int oe = myE ^ k;
            rank += (ou > u) || (ou == u && oe < myE);
        }
        // pref word: expert myE occupies nibble 4*rank
        unsigned lo = (rank < 8)  ? ((unsigned)myE << (4 * rank))       : 0u;
        unsigned hi = (rank >= 8) ? ((unsigned)myE << (4 * (rank - 8))) : 0u;
#pragma unroll
        for (int o = 1; o < 16; o <<= 1) {
            lo |= __shfl_xor_sync(FULLM, lo, o);
            hi |= __shfl_xor_sync(FULLM, hi, o);
        }
        if (myE == 0) g_prefs[t] = (u64)lo | ((u64)hi << 32);
    }
}

// =====================================================================
// Kernel 2: phased balanced assignment v7 (unchanged — control)
// =====================================================================
#define S_PREF_OFF 0
#define S_CH_OFF   65536
#define S_BLK_OFF  73728                 // [16][32] int
#define S_BPRE_OFF (73728 + 2048)        // [16][32] int
#define S_WCNT_OFF (73728 + 4096)        // [32][16] int
#define S_INT_OFF  (73728 + 6144)
#define SMEM_BYTES (73728 + 6144 + 128)
// s_int: [16] active, [17] start, [18] cut A, [19] cut B

__global__ void __launch_bounds__(1024) assign_kernel(float* __restrict__ out) {
    extern __shared__ unsigned char smem[];
    u64*      s_pref = (u64*)(smem + S_PREF_OFF);
    unsigned* s_ch   = (unsigned*)(smem + S_CH_OFF);   // 2048 words
    int*      s_blk  = (int*)(smem + S_BLK_OFF);
    int*      s_bpre = (int*)(smem + S_BPRE_OFF);
    int*      s_wcnt = (int*)(smem + S_WCNT_OFF);
    int*      s_int  = (int*)(smem + S_INT_OFF);

    const int tid  = threadIdx.x;
    const int lane = tid & 31;
    const int wid  = tid >> 5;
    const unsigned ltm = (1u << lane) - 1u;

    for (int i = tid; i < NT; i += 1024) s_pref[i] = g_prefs[i];
    if (tid == 0) { s_int[16] = 0xFFFF; s_int[17] = 0; s_int[18] = CINF; s_int[19] = CINF; }
    __syncthreads();

    // ---- build: warp wid counts+writes its 256-token block ----
    {
        u64 c0 = 0, c1 = 0, c2 = 0, c3 = 0;
#pragma unroll
        for (int i = 0; i < 2; ++i) {
            const int w = wid * 64 + i * 32 + lane;
            unsigned word = 0;
#pragma unroll
            for (int bb = 0; bb < 4; ++bb) {
                const int c = (int)(s_pref[w * 4 + bb] & 15);
                word |= (unsigned)c << (bb * 8);
                const u64 inc = 1ull << ((c & 3) << 4);
                if      ((c >> 2) == 0) c0 += inc;
                else if ((c >> 2) == 1) c1 += inc;
                else if ((c >> 2) == 2) c2 += inc;
                else                    c3 += inc;
            }
            s_ch[w] = word;
        }
#pragma unroll
        for (int o = 16; o; o >>= 1) {
            c0 += __shfl_xor_sync(FULLM, c0, o);
            c1 += __shfl_xor_sync(FULLM, c1, o);
            c2 += __shfl_xor_sync(FULLM, c2, o);
            c3 += __shfl_xor_sync(FULLM, c3, o);
        }
        if (lane < NE) {
            const u64 sel = (lane >> 2) == 0 ? c0 : (lane >> 2) == 1 ? c1
                          : (lane >> 2) == 2 ? c2 : c3;
            s_blk[lane * 32 + wid] = (int)((sel >> ((lane & 3) << 4)) & 0xFFFF);
        }
    }
    __syncthreads();

    // ---------------- phase loop ----------------
    for (int phase = 0; phase < NE; ++phase) {
        const int s = s_int[17];
        const int active  = s_int[16];
        const int cutslot = 18 + (phase & 1);

        if (wid < NE && ((active >> wid) & 1)) {
            const int e = wid;
            const unsigned splat = (unsigned)e * 0x01010101u;
            const int pb   = s >> 8;
            const int ws   = s >> 2;
            const int we_  = (pb + 1) * 64;
            const unsigned mfirst = 0xFFFFFFFFu << ((s & 3) * 8);

            const int i0 = ws + lane * 2;
            unsigned cm0 = 0, cm1 = 0;
            if (i0 < we_) {
                cm0 = __vcmpeq4(s_ch[i0], splat);
                if (i0 == ws) cm0 &= mfirst;
            }
            if (i0 + 1 < we_) cm1 = __vcmpeq4(s_ch[i0 + 1], splat);
            const int lcnt = (__popc(cm0) + __popc(cm1)) >> 3;
            const int ptotal = (int)__reduce_add_sync(FULLM, (unsigned)lcnt);

            const int bfull = s_blk[e * 32 + lane];
            int incl = bfull;
#pragma unroll
            for (int o = 1; o < 32; o <<= 1) {
                const int u = __shfl_up_sync(FULLM, incl, o);
                if (lane >= o) incl += u;
            }
            const int tot     = __shfl_sync(FULLM, incl, 31);
            const int pref_pb = __shfl_sync(FULLM, incl, pb);
            const int need    = CAP - (pref_pb - ptotal);
            const int live    = tot - pref_pb + ptotal;

            if (live >= need) {
                if (ptotal >= need) {
                    int linc = lcnt;
#pragma unroll
                    for (int o = 1; o < 32; o <<= 1) {
                        const int u = __shfl_up_sync(FULLM, linc, o);
                        if (lane >= o) linc += u;
                    }
                    const unsigned bal = __ballot_sync(FULLM, linc >= need);
                    const int cl = __ffs(bal) - 1;
                    if (lane == cl) {
                        int rem = need - (linc - lcnt);
                        int pos = -1;
#pragma unroll
                        for (int bb = 0; bb < 4 && pos < 0; ++bb)
                            if ((cm0 >> (bb * 8)) & 1u && --rem == 0) pos = i0 * 4 + bb;
#pragma unroll
                        for (int bb = 0; bb < 4 && pos < 0; ++bb)
                            if ((cm1 >> (bb * 8)) & 1u && --rem == 0) pos = (i0 + 1) * 4 + bb;
                        atomicMin(&s_int[cutslot], (pos << 4) | e);
                    }
                } else {
                    const int rem2 = need - ptotal;
                    const int minc = incl - pref_pb;
                    const unsigned bal = __ballot_sync(FULLM, lane > pb && minc >= rem2);
                    const int kc   = __ffs(bal) - 1;
                    const int excl = __shfl_sync(FULLM, incl - bfull, kc) - pref_pb;
                    const int rem3 = rem2 - excl;
                    const int j0 = kc * 64 + lane * 2;
                    const unsigned d0 = __vcmpeq4(s_ch[j0], splat);
                    const unsigned d1 = __vcmpeq4(s_ch[j0 + 1], splat);
                    const int lc = (__popc(d0) + __popc(d1)) >> 3;
                    int li = lc;
#pragma unroll
                    for (int o = 1; o < 32; o <<= 1) {
                        const int u = __shfl_up_sync(FULLM, li, o);
                        if (lane >= o) li += u;
                    }
                    const unsigned bal2 = __ballot_sync(FULLM, li >= rem3);
                    const int cl2 = __ffs(bal2) - 1;
                    if (lane == cl2) {
                        int rem = rem3 - (li - lc);
                        int pos = -1;
#pragma unroll
                        for (int bb = 0; bb < 4 && pos < 0; ++bb)
                            if ((d0 >> (bb * 8)) & 1u && --rem == 0) pos = j0 * 4 + bb;
#pragma unroll
                        for (int bb = 0; bb < 4 && pos < 0; ++bb)
                            if ((d1 >> (bb * 8)) & 1u && --rem == 0) pos = (j0 + 1) * 4 + bb;
                        atomicMin(&s_int[cutslot], (pos << 4) | e);
                    }
                }
            }
        }
        __syncthreads();                               // B1: cut final

        const int mv = s_int[cutslot];
        if (mv == CINF) {
            if (tid == 0) s_int[17] = NT;
            __syncthreads();
            continue;
        }
        const int pstar = mv >> 4, es = mv & 15;
        const int nactive = active & ~(1 << es);

        if (tid == 0) {
            s_int[16] = nactive;
            s_int[17] = pstar + 1;
            s_int[cutslot] = CINF;
        }
        {
            const int sn = pstar + 1;
            const int ws = sn >> 2;
            const unsigned splat = (unsigned)es * 0x01010101u;
            const unsigned mfirst = 0xFFFFFFFFu << ((sn & 3) * 8);
            for (int w = ws + tid; w < 2048; w += 1024) {
                unsigned word = s_ch[w];
                unsigned m = __vcmpeq4(word, splat);
                if (w == ws) m &= mfirst;
                if (m) {
                    const int blk = w >> 6;
                    int moved = 0;
                    do {
                        const int bb = (__ffs(m) - 1) >> 3;
                        m &= ~(0xFFu << (bb * 8));
                        u64 p = s_pref[w * 4 + bb];
                        int c = (int)(p & 15);
                        while (!((nactive >> c) & 1)) { p >>= 4; c = (int)(p & 15); }
                        word = (word & ~(0xFFu << (bb * 8))) | ((unsigned)c << (bb * 8));
                        atomicAdd(&s_blk[c * 32 + blk], 1);
                        ++moved;
                    } while (m);
                    atomicAdd(&s_blk[es * 32 + blk], -moved);
                    s_ch[w] = word;
                }
            }
        }
        __syncthreads();                               // B2: phase done
    }

    // ---------------- epilogue: rank via block prefixes + match_any ----------------
    if (wid < NE) {
        const int v = s_blk[wid * 32 + lane];
        int inc = v;
#pragma unroll
        for (int o = 1; o < 32; o <<= 1) {
            const int u = __shfl_up_sync(FULLM, inc, o);
            if (lane >= o) inc += u;
        }
        s_bpre[wid * 32 + lane] = wid * CAP + inc - v;
    }
    if (lane < NE) s_wcnt[wid * 16 + lane] = 0;
    __syncthreads();

    {
        const int base = wid * 256;
#pragma unroll
        for (int j = 0; j < 8; ++j) {
            const int t = base + j * 32 + lane;
            const int e = (int)((s_ch[t >> 2] >> ((t & 3) * 8)) & 0xFFu);
            const unsigned mask = __match_any_sync(FULLM, e);
            const int leader = __ffs(mask) - 1;
            int old = 0;
            if (lane == leader) old = atomicAdd(&s_wcnt[wid * 16 + e], __popc(mask));
            old = __shfl_sync(FULLM, old, leader);
            const int rank = s_bpre[e * 32 + wid] + old + __popc(mask & ltm);
            out[rank] = (float)t;
            out[NT + t] = g_probsT[e * NT + t];
        }
    }
}

// =====================================================================
extern "C" void kernel_launch(void* const* d_in, const int* in_sizes, int n_in,
                              void* d_out, int out_size) {
    const float* f = (const float*)d_in[0];   // features [8192, 2048] f32
    const float* W = (const float*)d_in[1];   // gate weight [16, 2048] f32
    const float* b = (const float*)d_in[2];   // bias [16] f32
    float* out = (float*)d_out;               // [8192] sort_by_expert ++ [8192] gathered

    gemv_kernel<<<NT / 16, 128>>>(f, W, b);

    cudaFuncSetAttribute(assign_kernel,
                         cudaFuncAttributeMaxDynamicSharedMemorySize, SMEM_BYTES);
    assign_kernel<<<1, 1024, SMEM_BYTES>>>(out);
}

// round 10
// speedup vs baseline: 1.2593x; 1.2593x over previous
#include <cuda_runtime.h>

#define NT 8192
#define ND 2048
#define NE 16
#define CAP 512
#define FULLM 0xFFFFFFFFu
#define CINF 0x7FFFFFFF

typedef unsigned long long u64;

__device__ float g_probsT[NE * NT];  // softmax probs, transposed [e][t]
__device__ u64   g_prefs[NT];        // packed expert-preference order (16 nibbles)

__device__ __forceinline__ u64 ffma2(u64 a, u64 b, u64 c) {
    u64 d;
    asm("fma.rn.f32x2 %0, %1, %2, %3;" : "=l"(d) : "l"(a), "l"(b), "l"(c));
    return d;
}

// =====================================================================
// Kernel 1: GEMV + parallel epilogue (no reg cap — R9's cap caused spills)
// =====================================================================
__global__ void __launch_bounds__(128) gemv_kernel(const float* __restrict__ f,
                                                   const float* __restrict__ W,
                                                   const float* __restrict__ b) {
    const int lane = threadIdx.x & 31;
    const int wid  = threadIdx.x >> 5;
    const int t0   = (blockIdx.x * 4 + wid) * 4;

    const ulonglong2* F  = reinterpret_cast<const ulonglong2*>(f + (size_t)t0 * ND);
    const ulonglong2* Wv = reinterpret_cast<const ulonglong2*>(W);

    u64 acc[4][NE];
#pragma unroll
    for (int t = 0; t < 4; ++t)
#pragma unroll
        for (int e = 0; e < NE; ++e) acc[t][e] = 0ull;

#pragma unroll 2
    for (int i = 0; i < 16; ++i) {
        const int k = i * 32 + lane;
        const ulonglong2 a0 = F[k];
        const ulonglong2 a1 = F[k + 512];
        const ulonglong2 a2 = F[k + 1024];
        const ulonglong2 a3 = F[k + 1536];
#pragma unroll
        for (int e = 0; e < NE; ++e) {
            const ulonglong2 w = Wv[e * 512 + k];
            acc[0][e] = ffma2(a0.x, w.x, acc[0][e]);
            acc[0][e] = ffma2(a0.y, w.y, acc[0][e]);
            acc[1][e] = ffma2(a1.x, w.x, acc[1][e]);
            acc[1][e] = ffma2(a1.y, w.y, acc[1][e]);
            acc[2][e] = ffma2(a2.x, w.x, acc[2][e]);
            acc[2][e] = ffma2(a2.y, w.y, acc[2][e]);
            acc[3][e] = ffma2(a3.x, w.x, acc[3][e]);
            acc[3][e] = ffma2(a3.y, w.y, acc[3][e]);
        }
    }

    // reduce; lane (t = lane>>4 [+2], e = lane&15) keeps its two values
    const int myE = lane & 15;
    const int myT = lane >> 4;
    float v0 = 0.f, v1 = 0.f;
#pragma unroll
    for (int t = 0; t < 4; ++t) {
#pragma unroll
        for (int e = 0; e < NE; ++e) {
            float sv = __uint_as_float((unsigned)acc[t][e]) +
                       __uint_as_float((unsigned)(acc[t][e] >> 32));
#pragma unroll
            for (int o = 16; o; o >>= 1) sv += __shfl_xor_sync(FULLM, sv, o);
            if (e == myE) {
                if (t == myT)     v0 = sv;
                if (t == myT + 2) v1 = sv;
            }
        }
    }

    const float bias = __ldg(b + myE);
#pragma unroll
    for (int p = 0; p < 2; ++p) {
        const int t = t0 + myT + 2 * p;
        const float a = (p ? v1 : v0) + bias;

        // softmax over the 16-lane group
        float m = a;
#pragma unroll
        for (int o = 1; o < 16; o <<= 1) m = fmaxf(m, __shfl_xor_sync(FULLM, m, o));
        const float ex = __expf(a - m);
        float s = ex;
#pragma unroll
        for (int o = 1; o < 16; o <<= 1) s += __shfl_xor_sync(FULLM, s, o);
        g_probsT[myE * NT + t] = __fdividef(ex, s);

        // sortable key + rank (descending score, tie -> lower expert first)
        unsigned u = __float_as_uint(a);
        u = (u & 0x80000000u) ? ~u : (u | 0x80000000u);
        int rank = 0;
#pragma unroll
        for (int k = 1; k < 16; ++k) {
            const unsigned ou = __shfl_xor_sync(FULLM, u, k);
            const int oe = myE ^ k;
            rank += (ou > u) || (ou == u && oe < myE);
        }
        unsigned lo = (rank < 8)  ? ((unsigned)myE << (4 * rank))       : 0u;
        unsigned hi = (rank >= 8) ? ((unsigned)myE << (4 * (rank - 8))) : 0u;
#pragma unroll
        for (int o = 1; o < 16; o <<= 1) {
            lo |= __shfl_xor_sync(FULLM, lo, o);
            hi |= __shfl_xor_sync(FULLM, hi, o);
        }
        if (myE == 0) g_prefs[t] = (u64)lo | ((u64)hi << 32);
    }
}

// dummy launch-pattern shifter: makes ncu's launch #6 land on gemv_kernel
__global__ void dummy_kernel() {}

// =====================================================================
// Kernel 2: phased balanced assignment v7 (unchanged)
// =====================================================================
#define S_PREF_OFF 0
#define S_CH_OFF   65536
#define S_BLK_OFF  73728                 // [16][32] int
#define S_BPRE_OFF (73728 + 2048)        // [16][32] int
#define S_WCNT_OFF (73728 + 4096)        // [32][16] int
#define S_INT_OFF  (73728 + 6144)
#define SMEM_BYTES (73728 + 6144 + 128)
// s_int: [16] active, [17] start, [18] cut A, [19] cut B

__global__ void __launch_bounds__(1024) assign_kernel(float* __restrict__ out) {
    extern __shared__ unsigned char smem[];
    u64*      s_pref = (u64*)(smem + S_PREF_OFF);
    unsigned* s_ch   = (unsigned*)(smem + S_CH_OFF);   // 2048 words
    int*      s_blk  = (int*)(smem + S_BLK_OFF);
    int*      s_bpre = (int*)(smem + S_BPRE_OFF);
    int*      s_wcnt = (int*)(smem + S_WCNT_OFF);
    int*      s_int  = (int*)(smem + S_INT_OFF);

    const int tid  = threadIdx.x;
    const int lane = tid & 31;
    const int wid  = tid >> 5;
    const unsigned ltm = (1u << lane) - 1u;

    for (int i = tid; i < NT; i += 1024) s_pref[i] = g_prefs[i];
    if (tid == 0) { s_int[16] = 0xFFFF; s_int[17] = 0; s_int[18] = CINF; s_int[19] = CINF; }
    __syncthreads();

    // ---- build: warp wid counts+writes its 256-token block ----
    {
        u64 c0 = 0, c1 = 0, c2 = 0, c3 = 0;
#pragma unroll
        for (int i = 0; i < 2; ++i) {
            const int w = wid * 64 + i * 32 + lane;
            unsigned word = 0;
#pragma unroll
            for (int bb = 0; bb < 4; ++bb) {
                const int c = (int)(s_pref[w * 4 + bb] & 15);
                word |= (unsigned)c << (bb * 8);
                const u64 inc = 1ull << ((c & 3) << 4);
                if      ((c >> 2) == 0) c0 += inc;
                else if ((c >> 2) == 1) c1 += inc;
                else if ((c >> 2) == 2) c2 += inc;
                else                    c3 += inc;
            }
            s_ch[w] = word;
        }
#pragma unroll
        for (int o = 16; o; o >>= 1) {
            c0 += __shfl_xor_sync(FULLM, c0, o);
            c1 += __shfl_xor_sync(FULLM, c1, o);
            c2 += __shfl_xor_sync(FULLM, c2, o);
            c3 += __shfl_xor_sync(FULLM, c3, o);
        }
        if (lane < NE) {
            const u64 sel = (lane >> 2) == 0 ? c0 : (lane >> 2) == 1 ? c1
                          : (lane >> 2) == 2 ? c2 : c3;
            s_blk[lane * 32 + wid] = (int)((sel >> ((lane & 3) << 4)) & 0xFFFF);
        }
    }
    __syncthreads();

    // ---------------- phase loop ----------------
    for (int phase = 0; phase < NE; ++phase) {
        const int s = s_int[17];
        const int active  = s_int[16];
        const int cutslot = 18 + (phase & 1);

        if (wid < NE && ((active >> wid) & 1)) {
            const int e = wid;
            const unsigned splat = (unsigned)e * 0x01010101u;
            const int pb   = s >> 8;
            const int ws   = s >> 2;
            const int we_  = (pb + 1) * 64;
            const unsigned mfirst = 0xFFFFFFFFu << ((s & 3) * 8);

            const int i0 = ws + lane * 2;
            unsigned cm0 = 0, cm1 = 0;
            if (i0 < we_) {
                cm0 = __vcmpeq4(s_ch[i0], splat);
                if (i0 == ws) cm0 &= mfirst;
            }
            if (i0 + 1 < we_) cm1 = __vcmpeq4(s_ch[i0 + 1], splat);
            const int lcnt = (__popc(cm0) + __popc(cm1)) >> 3;
            const int ptotal = (int)__reduce_add_sync(FULLM, (unsigned)lcnt);

            const int bfull = s_blk[e * 32 + lane];
            int incl = bfull;
#pragma unroll
            for (int o = 1; o < 32; o <<= 1) {
                const int u = __shfl_up_sync(FULLM, incl, o);
                if (lane >= o) incl += u;
            }
            const int tot     = __shfl_sync(FULLM, incl, 31);
            const int pref_pb = __shfl_sync(FULLM, incl, pb);
            const int need    = CAP - (pref_pb - ptotal);
            const int live    = tot - pref_pb + ptotal;

            if (live >= need) {
                if (ptotal >= need) {
                    int linc = lcnt;
#pragma unroll
                    for (int o = 1; o < 32; o <<= 1) {
                        const int u = __shfl_up_sync(FULLM, linc, o);
                        if (lane >= o) linc += u;
                    }
                    const unsigned bal = __ballot_sync(FULLM, linc >= need);
                    const int cl = __ffs(bal) - 1;
                    if (lane == cl) {
                        int rem = need - (linc - lcnt);
                        int pos = -1;
#pragma unroll
                        for (int bb = 0; bb < 4 && pos < 0; ++bb)
                            if ((cm0 >> (bb * 8)) & 1u && --rem == 0) pos = i0 * 4 + bb;
#pragma unroll
                        for (int bb = 0; bb < 4 && pos < 0; ++bb)
                            if ((cm1 >> (bb * 8)) & 1u && --rem == 0) pos = (i0 + 1) * 4 + bb;
                        atomicMin(&s_int[cutslot], (pos << 4) | e);
                    }
                } else {
                    const int rem2 = need - ptotal;
                    const int minc = incl - pref_pb;
                    const unsigned bal = __ballot_sync(FULLM, lane > pb && minc >= rem2);
                    const int kc   = __ffs(bal) - 1;
                    const int excl = __shfl_sync(FULLM, incl - bfull, kc) - pref_pb;
                    const int rem3 = rem2 - excl;
                    const int j0 = kc * 64 + lane * 2;
                    const unsigned d0 = __vcmpeq4(s_ch[j0], splat);
                    const unsigned d1 = __vcmpeq4(s_ch[j0 + 1], splat);
                    const int lc = (__popc(d0) + __popc(d1)) >> 3;
                    int li = lc;
#pragma unroll
                    for (int o = 1; o < 32; o <<= 1) {
                        const int u = __shfl_up_sync(FULLM, li, o);
                        if (lane >= o) li += u;
                    }
                    const unsigned bal2 = __ballot_sync(FULLM, li >= rem3);
                    const int cl2 = __ffs(bal2) - 1;
                    if (lane == cl2) {
                        int rem = rem3 - (li - lc);
                        int pos = -1;
#pragma unroll
                        for (int bb = 0; bb < 4 && pos < 0; ++bb)
                            if ((d0 >> (bb * 8)) & 1u && --rem == 0) pos = j0 * 4 + bb;
#pragma unroll
                        for (int bb = 0; bb < 4 && pos < 0; ++bb)
                            if ((d1 >> (bb * 8)) & 1u && --rem == 0) pos = (j0 + 1) * 4 + bb;
                        atomicMin(&s_int[cutslot], (pos << 4) | e);
                    }
                }
            }
        }
        __syncthreads();                               // B1: cut final

        const int mv = s_int[cutslot];
        if (mv == CINF) {
            if (tid == 0) s_int[17] = NT;
            __syncthreads();
            continue;
        }
        const int pstar = mv >> 4, es = mv & 15;
        const int nactive = active & ~(1 << es);

        if (tid == 0) {
            s_int[16] = nactive;
            s_int[17] = pstar + 1;
            s_int[cutslot] = CINF;
        }
        {
            const int sn = pstar + 1;
            const int ws = sn >> 2;
            const unsigned splat = (unsigned)es * 0x01010101u;
            const unsigned mfirst = 0xFFFFFFFFu << ((sn & 3) * 8);
            for (int w = ws + tid; w < 2048; w += 1024) {
                unsigned word = s_ch[w];
                unsigned m = __vcmpeq4(word, splat);
                if (w == ws) m &= mfirst;
                if (m) {
                    const int blk = w >> 6;
                    int moved = 0;
                    do {
                        const int bb = (__ffs(m) - 1) >> 3;
                        m &= ~(0xFFu << (bb * 8));
                        u64 p = s_pref[w * 4 + bb];
                        int c = (int)(p & 15);
                        while (!((nactive >> c) & 1)) { p >>= 4; c = (int)(p & 15); }
                        word = (word & ~(0xFFu << (bb * 8))) | ((unsigned)c << (bb * 8));
                        atomicAdd(&s_blk[c * 32 + blk], 1);
                        ++moved;
                    } while (m);
                    atomicAdd(&s_blk[es * 32 + blk], -moved);
                    s_ch[w] = word;
                }
            }
        }
        __syncthreads();                               // B2: phase done
    }

    // ---------------- epilogue: rank via block prefixes + match_any ----------------
    if (wid < NE) {
        const int v = s_blk[wid * 32 + lane];
        int inc = v;
#pragma unroll
        for (int o = 1; o < 32; o <<= 1) {
            const int u = __shfl_up_sync(FULLM, inc, o);
            if (lane >= o) inc += u;
        }
        s_bpre[wid * 32 + lane] = wid * CAP + inc - v;
    }
    if (lane < NE) s_wcnt[wid * 16 + lane] = 0;
    __syncthreads();

    {
        const int base = wid * 256;
#pragma unroll
        for (int j = 0; j < 8; ++j) {
            const int t = base + j * 32 + lane;
            const int e = (int)((s_ch[t >> 2] >> ((t & 3) * 8)) & 0xFFu);
            const unsigned mask = __match_any_sync(FULLM, e);
            const int leader = __ffs(mask) - 1;
            int old = 0;
            if (lane == leader) old = atomicAdd(&s_wcnt[wid * 16 + e], __popc(mask));
            old = __shfl_sync(FULLM, old, leader);
            const int rank = s_bpre[e * 32 + wid] + old + __popc(mask & ltm);
            out[rank] = (float)t;
            out[NT + t] = g_probsT[e * NT + t];
        }
    }
}

// =====================================================================
extern "C" void kernel_launch(void* const* d_in, const int* in_sizes, int n_in,
                              void* d_out, int out_size) {
    const float* f = (const float*)d_in[0];   // features [8192, 2048] f32
    const float* W = (const float*)d_in[1];   // gate weight [16, 2048] f32
    const float* b = (const float*)d_in[2];   // bias [16] f32
    float* out = (float*)d_out;               // [8192] sort_by_expert ++ [8192] gathered

    gemv_kernel<<<NT / 16, 128>>>(f, W, b);

    cudaFuncSetAttribute(assign_kernel,
                         cudaFuncAttributeMaxDynamicSharedMemorySize, SMEM_BYTES);
    assign_kernel<<<1, 1024, SMEM_BYTES>>>(out);

    // period-5 launch pattern: ncu (-s 5 -c 1) lands on the NEXT call's
    // gemv_kernel instead of assign_kernel. Diagnostic only.
    dummy_kernel<<<1, 32>>>();
    dummy_kernel<<<1, 32>>>();
    dummy_kernel<<<1, 32>>>();
}

// round 11
// speedup vs baseline: 1.3248x; 1.0520x over previous
#include <cuda_runtime.h>

#define NT 8192
#define ND 2048
#define NE 16
#define CAP 512
#define FULLM 0xFFFFFFFFu
#define CINF 0x7FFFFFFF

typedef unsigned long long u64;

__device__ float g_probsT[NE * NT];  // softmax probs, transposed [e][t]
__device__ u64   g_prefs[NT];        // packed expert-preference order (16 nibbles)

__device__ __forceinline__ u64 ffma2(u64 a, u64 b, u64 c) {
    u64 d;
    asm("fma.rn.f32x2 %0, %1, %2, %3;" : "=l"(d) : "l"(a), "l"(b), "l"(c));
    return d;
}

// streaming (evict-first) 16B load — keeps single-use features out of L1
__device__ __forceinline__ ulonglong2 ldcs2(const ulonglong2* p) {
    ulonglong2 v;
    asm("ld.global.cs.v2.u64 {%0, %1}, [%2];" : "=l"(v.x), "=l"(v.y) : "l"(p));
    return v;
}
// L1-resident 16B load for W (read-only, reused by every warp)
__device__ __forceinline__ ulonglong2 ldg2(const ulonglong2* p) {
    ulonglong2 v;
    asm("ld.global.nc.v2.u64 {%0, %1}, [%2];" : "=l"(v.x), "=l"(v.y) : "l"(p));
    return v;
}

// =====================================================================
// Kernel 1: GEMV + parallel epilogue. Features streamed (.cs), W via L1.
// =====================================================================
__global__ void __launch_bounds__(128) gemv_kernel(const float* __restrict__ f,
                                                   const float* __restrict__ W,
                                                   const float* __restrict__ b) {
    const int lane = threadIdx.x & 31;
    const int wid  = threadIdx.x >> 5;
    const int t0   = (blockIdx.x * 4 + wid) * 4;

    const ulonglong2* F  = reinterpret_cast<const ulonglong2*>(f + (size_t)t0 * ND);
    const ulonglong2* Wv = reinterpret_cast<const ulonglong2*>(W);

    u64 acc[4][NE];
#pragma unroll
    for (int t = 0; t < 4; ++t)
#pragma unroll
        for (int e = 0; e < NE; ++e) acc[t][e] = 0ull;

#pragma unroll 2
    for (int i = 0; i < 16; ++i) {
        const int k = i * 32 + lane;
        const ulonglong2 a0 = ldcs2(F + k);
        const ulonglong2 a1 = ldcs2(F + k + 512);
        const ulonglong2 a2 = ldcs2(F + k + 1024);
        const ulonglong2 a3 = ldcs2(F + k + 1536);
#pragma unroll
        for (int e = 0; e < NE; ++e) {
            const ulonglong2 w = ldg2(Wv + e * 512 + k);
            acc[0][e] = ffma2(a0.x, w.x, acc[0][e]);
            acc[0][e] = ffma2(a0.y, w.y, acc[0][e]);
            acc[1][e] = ffma2(a1.x, w.x, acc[1][e]);
            acc[1][e] = ffma2(a1.y, w.y, acc[1][e]);
            acc[2][e] = ffma2(a2.x, w.x, acc[2][e]);
            acc[2][e] = ffma2(a2.y, w.y, acc[2][e]);
            acc[3][e] = ffma2(a3.x, w.x, acc[3][e]);
            acc[3][e] = ffma2(a3.y, w.y, acc[3][e]);
        }
    }

    // reduce; lane (t = lane>>4 [+2], e = lane&15) keeps its two values
    const int myE = lane & 15;
    const int myT = lane >> 4;
    float v0 = 0.f, v1 = 0.f;
#pragma unroll
    for (int t = 0; t < 4; ++t) {
#pragma unroll
        for (int e = 0; e < NE; ++e) {
            float sv = __uint_as_float((unsigned)acc[t][e]) +
                       __uint_as_float((unsigned)(acc[t][e] >> 32));
#pragma unroll
            for (int o = 16; o; o >>= 1) sv += __shfl_xor_sync(FULLM, sv, o);
            if (e == myE) {
                if (t == myT)     v0 = sv;
                if (t == myT + 2) v1 = sv;
            }
        }
    }

    const float bias = __ldg(b + myE);
#pragma unroll
    for (int p = 0; p < 2; ++p) {
        const int t = t0 + myT + 2 * p;
        const float a = (p ? v1 : v0) + bias;

        // softmax over the 16-lane group
        float m = a;
#pragma unroll
        for (int o = 1; o < 16; o <<= 1) m = fmaxf(m, __shfl_xor_sync(FULLM, m, o));
        const float ex = __expf(a - m);
        float s = ex;
#pragma unroll
        for (int o = 1; o < 16; o <<= 1) s += __shfl_xor_sync(FULLM, s, o);
        g_probsT[myE * NT + t] = __fdividef(ex, s);

        // sortable key + rank (descending score, tie -> lower expert first)
        unsigned u = __float_as_uint(a);
        u = (u & 0x80000000u) ? ~u : (u | 0x80000000u);
        int rank = 0;
#pragma unroll
        for (int k = 1; k < 16; ++k) {
            const unsigned ou = __shfl_xor_sync(FULLM, u, k);
            const int oe = myE ^ k;
            rank += (ou > u) || (ou == u && oe < myE);
        }
        unsigned lo = (rank < 8)  ? ((unsigned)myE << (4 * rank))       : 0u;
        unsigned hi = (rank >= 8) ? ((unsigned)myE << (4 * (rank - 8))) : 0u;
#pragma unroll
        for (int o = 1; o < 16; o <<= 1) {
            lo |= __shfl_xor_sync(FULLM, lo, o);
            hi |= __shfl_xor_sync(FULLM, hi, o);
        }
        if (myE == 0) g_prefs[t] = (u64)lo | ((u64)hi << 32);
    }
}

// =====================================================================
// Kernel 2: phased balanced assignment v7 (unchanged)
// =====================================================================
#define S_PREF_OFF 0
#define S_CH_OFF   65536
#define S_BLK_OFF  73728                 // [16][32] int
#define S_BPRE_OFF (73728 + 2048)        // [16][32] int
#define S_WCNT_OFF (73728 + 4096)        // [32][16] int
#define S_INT_OFF  (73728 + 6144)
#define SMEM_BYTES (73728 + 6144 + 128)
// s_int: [16] active, [17] start, [18] cut A, [19] cut B

__global__ void __launch_bounds__(1024) assign_kernel(float* __restrict__ out) {
    extern __shared__ unsigned char smem[];
    u64*      s_pref = (u64*)(smem + S_PREF_OFF);
    unsigned* s_ch   = (unsigned*)(smem + S_CH_OFF);   // 2048 words
    int*      s_blk  = (int*)(smem + S_BLK_OFF);
    int*      s_bpre = (int*)(smem + S_BPRE_OFF);
    int*      s_wcnt = (int*)(smem + S_WCNT_OFF);
    int*      s_int  = (int*)(smem + S_INT_OFF);

    const int tid  = threadIdx.x;
    const int lane = tid & 31;
    const int wid  = tid >> 5;
    const unsigned ltm = (1u << lane) - 1u;

    for (int i = tid; i < NT; i += 1024) s_pref[i] = g_prefs[i];
    if (tid == 0) { s_int[16] = 0xFFFF; s_int[17] = 0; s_int[18] = CINF; s_int[19] = CINF; }
    __syncthreads();

    // ---- build: warp wid counts+writes its 256-token block ----
    {
        u64 c0 = 0, c1 = 0, c2 = 0, c3 = 0;
#pragma unroll
        for (int i = 0; i < 2; ++i) {
            const int w = wid * 64 + i * 32 + lane;
            unsigned word = 0;
#pragma unroll
            for (int bb = 0; bb < 4; ++bb) {
                const int c = (int)(s_pref[w * 4 + bb] & 15);
                word |= (unsigned)c << (bb * 8);
                const u64 inc = 1ull << ((c & 3) << 4);
                if      ((c >> 2) == 0) c0 += inc;
                else if ((c >> 2) == 1) c1 += inc;
                else if ((c >> 2) == 2) c2 += inc;
                else                    c3 += inc;
            }
            s_ch[w] = word;
        }
#pragma unroll
        for (int o = 16; o; o >>= 1) {
            c0 += __shfl_xor_sync(FULLM, c0, o);
            c1 += __shfl_xor_sync(FULLM, c1, o);
            c2 += __shfl_xor_sync(FULLM, c2, o);
            c3 += __shfl_xor_sync(FULLM, c3, o);
        }
        if (lane < NE) {
            const u64 sel = (lane >> 2) == 0 ? c0 : (lane >> 2) == 1 ? c1
                          : (lane >> 2) == 2 ? c2 : c3;
            s_blk[lane * 32 + wid] = (int)((sel >> ((lane & 3) << 4)) & 0xFFFF);
        }
    }
    __syncthreads();

    // ---------------- phase loop ----------------
    for (int phase = 0; phase < NE; ++phase) {
        const int s = s_int[17];
        const int active  = s_int[16];
        const int cutslot = 18 + (phase & 1);

        if (wid < NE && ((active >> wid) & 1)) {
            const int e = wid;
            const unsigned splat = (unsigned)e * 0x01010101u;
            const int pb   = s >> 8;
            const int ws   = s >> 2;
            const int we_  = (pb + 1) * 64;
            const unsigned mfirst = 0xFFFFFFFFu << ((s & 3) * 8);

            const int i0 = ws + lane * 2;
            unsigned cm0 = 0, cm1 = 0;
            if (i0 < we_) {
                cm0 = __vcmpeq4(s_ch[i0], splat);
                if (i0 == ws) cm0 &= mfirst;
            }
            if (i0 + 1 < we_) cm1 = __vcmpeq4(s_ch[i0 + 1], splat);
            const int lcnt = (__popc(cm0) + __popc(cm1)) >> 3;
            const int ptotal = (int)__reduce_add_sync(FULLM, (unsigned)lcnt);

            const int bfull = s_blk[e * 32 + lane];
            int incl = bfull;
#pragma unroll
            for (int o = 1; o < 32; o <<= 1) {
                const int u = __shfl_up_sync(FULLM, incl, o);
                if (lane >= o) incl += u;
            }
            const int tot     = __shfl_sync(FULLM, incl, 31);
            const int pref_pb = __shfl_sync(FULLM, incl, pb);
            const int need    = CAP - (pref_pb - ptotal);
            const int live    = tot - pref_pb + ptotal;

            if (live >= need) {
                if (ptotal >= need) {
                    int linc = lcnt;
#pragma unroll
                    for (int o = 1; o < 32; o <<= 1) {
                        const int u = __shfl_up_sync(FULLM, linc, o);
                        if (lane >= o) linc += u;
                    }
                    const unsigned bal = __ballot_sync(FULLM, linc >= need);
                    const int cl = __ffs(bal) - 1;
                    if (lane == cl) {
                        int rem = need - (linc - lcnt);
                        int pos = -1;
#pragma unroll
                        for (int bb = 0; bb < 4 && pos < 0; ++bb)
                            if ((cm0 >> (bb * 8)) & 1u && --rem == 0) pos = i0 * 4 + bb;
#pragma unroll
                        for (int bb = 0; bb < 4 && pos < 0; ++bb)
                            if ((cm1 >> (bb * 8)) & 1u && --rem == 0) pos = (i0 + 1) * 4 + bb;
                        atomicMin(&s_int[cutslot], (pos << 4) | e);
                    }
                } else {
                    const int rem2 = need - ptotal;
                    const int minc = incl - pref_pb;
                    const unsigned bal = __ballot_sync(FULLM, lane > pb && minc >= rem2);
                    const int kc   = __ffs(bal) - 1;
                    const int excl = __shfl_sync(FULLM, incl - bfull, kc) - pref_pb;
                    const int rem3 = rem2 - excl;
                    const int j0 = kc * 64 + lane * 2;
                    const unsigned d0 = __vcmpeq4(s_ch[j0], splat);
                    const unsigned d1 = __vcmpeq4(s_ch[j0 + 1], splat);
                    const int lc = (__popc(d0) + __popc(d1)) >> 3;
                    int li = lc;
#pragma unroll
                    for (int o = 1; o < 32; o <<= 1) {
                        const int u = __shfl_up_sync(FULLM, li, o);
                        if (lane >= o) li += u;
                    }
                    const unsigned bal2 = __ballot_sync(FULLM, li >= rem3);
                    const int cl2 = __ffs(bal2) - 1;
                    if (lane == cl2) {
                        int rem = rem3 - (li - lc);
                        int pos = -1;
#pragma unroll
                        for (int bb = 0; bb < 4 && pos < 0; ++bb)
                            if ((d0 >> (bb * 8)) & 1u && --rem == 0) pos = j0 * 4 + bb;
#pragma unroll
                        for (int bb = 0; bb < 4 && pos < 0; ++bb)
                            if ((d1 >> (bb * 8)) & 1u && --rem == 0) pos = (j0 + 1) * 4 + bb;
                        atomicMin(&s_int[cutslot], (pos << 4) | e);
                    }
                }
            }
        }
        __syncthreads();                               // B1: cut final

        const int mv = s_int[cutslot];
        if (mv == CINF) {
            if (tid == 0) s_int[17] = NT;
            __syncthreads();
            continue;
        }
        const int pstar = mv >> 4, es = mv & 15;
        const int nactive = active & ~(1 << es);

        if (tid == 0) {
            s_int[16] = nactive;
            s_int[17] = pstar + 1;
            s_int[cutslot] = CINF;
        }
        {
            const int sn = pstar + 1;
            const int ws = sn >> 2;
            const unsigned splat = (unsigned)es * 0x01010101u;
            const unsigned mfirst = 0xFFFFFFFFu << ((sn & 3) * 8);
            for (int w = ws + tid; w < 2048; w += 1024) {
                unsigned word = s_ch[w];
                unsigned m = __vcmpeq4(word, splat);
                if (w == ws) m &= mfirst;
                if (m) {
                    const int blk = w >> 6;
                    int moved = 0;
                    do {
                        const int bb = (__ffs(m) - 1) >> 3;
                        m &= ~(0xFFu << (bb * 8));
                        u64 p = s_pref[w * 4 + bb];
                        int c = (int)(p & 15);
                        while (!((nactive >> c) & 1)) { p >>= 4; c = (int)(p & 15); }
                        word = (word & ~(0xFFu << (bb * 8))) | ((unsigned)c << (bb * 8));
                        atomicAdd(&s_blk[c * 32 + blk], 1);
                        ++moved;
                    } while (m);
                    atomicAdd(&s_blk[es * 32 + blk], -moved);
                    s_ch[w] = word;
                }
            }
        }
        __syncthreads();                               // B2: phase done
    }

    // ---------------- epilogue: rank via block prefixes + match_any ----------------
    if (wid < NE) {
        const int v = s_blk[wid * 32 + lane];
        int inc = v;
#pragma unroll
        for (int o = 1; o < 32; o <<= 1) {
            const int u = __shfl_up_sync(FULLM, inc, o);
            if (lane >= o) inc += u;
        }
        s_bpre[wid * 32 + lane] = wid * CAP + inc - v;
    }
    if (lane < NE) s_wcnt[wid * 16 + lane] = 0;
    __syncthreads();

    {
        const int base = wid * 256;
#pragma unroll
        for (int j = 0; j < 8; ++j) {
            const int t = base + j * 32 + lane;
            const int e = (int)((s_ch[t >> 2] >> ((t & 3) * 8)) & 0xFFu);
            const unsigned mask = __match_any_sync(FULLM, e);
            const int leader = __ffs(mask) - 1;
            int old = 0;
            if (lane == leader) old = atomicAdd(&s_wcnt[wid * 16 + e], __popc(mask));
            old = __shfl_sync(FULLM, old, leader);
            const int rank = s_bpre[e * 32 + wid] + old + __popc(mask & ltm);
            out[rank] = (float)t;
            out[NT + t] = g_probsT[e * NT + t];
        }
    }
}

// =====================================================================
extern "C" void kernel_launch(void* const* d_in, const int* in_sizes, int n_in,
                              void* d_out, int out_size) {
    const float* f = (const float*)d_in[0];   // features [8192, 2048] f32
    const float* W = (const float*)d_in[1];   // gate weight [16, 2048] f32
    const float* b = (const float*)d_in[2];   // bias [16] f32
    float* out = (float*)d_out;               // [8192] sort_by_expert ++ [8192] gathered

    gemv_kernel<<<NT / 16, 128>>>(f, W, b);

    cudaFuncSetAttribute(assign_kernel,
                         cudaFuncAttributeMaxDynamicSharedMemorySize, SMEM_BYTES);
    assign_kernel<<<1, 1024, SMEM_BYTES>>>(out);
}

// round 12
// speedup vs baseline: 1.7286x; 1.3048x over previous
#include <cuda_runtime.h>

#define NT 8192
#define ND 2048
#define NE 16
#define CAP 512
#define FULLM 0xFFFFFFFFu
#define CINF 0x7FFFFFFF

typedef unsigned long long u64;

__device__ float g_probsT[NE * NT];            // softmax probs, transposed [e][t]
__device__ u64   g_prefs[NT];                  // packed preference order (16 nibbles)
__device__ __align__(16) u64 g_Wt[ND * NE / 2]; // swizzled W, expert-pair packed

__device__ __forceinline__ u64 ffma2(u64 a, u64 b, u64 c) {
    u64 d;
    asm("fma.rn.f32x2 %0, %1, %2, %3;" : "=l"(d) : "l"(a), "l"(b), "l"(c));
    return d;
}
__device__ __forceinline__ u64 addx2(u64 a, u64 b) {
    u64 d;
    asm("add.rn.f32x2 %0, %1, %2;" : "=l"(d) : "l"(a), "l"(b));
    return d;
}
__device__ __forceinline__ u64 splat2(float x) {
    u64 r;
    asm("mov.b64 %0, {%1, %1};" : "=l"(r) : "f"(x));
    return r;
}
__device__ __forceinline__ u64 shfl64_xor(u64 v, int m) {
    unsigned lo = (unsigned)v, hi = (unsigned)(v >> 32);
    lo = __shfl_xor_sync(FULLM, lo, m);
    hi = __shfl_xor_sync(FULLM, hi, m);
    return (u64)lo | ((u64)hi << 32);
}
__device__ __forceinline__ float4 ldcs4(const float4* p) {
    float4 v;
    asm("ld.global.cs.v4.f32 {%0,%1,%2,%3}, [%4];"
        : "=f"(v.x), "=f"(v.y), "=f"(v.z), "=f"(v.w) : "l"(p));
    return v;
}
__device__ __forceinline__ ulonglong2 ldg2(const ulonglong2* p) {
    ulonglong2 v;
    asm("ld.global.nc.v2.u64 {%0, %1}, [%2];" : "=l"(v.x), "=l"(v.y) : "l"(p));
    return v;
}

// =====================================================================
// Kernel 0: one-time W swizzle.  dst ulonglong2 index for (k, j):
//   i = k>>7, lane = (k>>2)&31, kk = k&3  ->  ((i*4+kk)*4 + j)*32 + lane
//   payload: pairs (experts 4j,4j+1) and (4j+2,4j+3) at column k.
// =====================================================================
__global__ void wprep_kernel(const float* __restrict__ W) {
    const int idx = blockIdx.x * 256 + threadIdx.x;   // 0..8191 = k*4 + j
    const int k = idx >> 2, j = idx & 3;
    const int i = k >> 7, ln = (k >> 2) & 31, kk = k & 3;
    const int dst = ((i * 4 + kk) * 4 + j) * 32 + ln;
    const float w0 = W[(4 * j + 0) * ND + k];
    const float w1 = W[(4 * j + 1) * ND + k];
    const float w2 = W[(4 * j + 2) * ND + k];
    const float w3 = W[(4 * j + 3) * ND + k];
    ulonglong2 v;
    v.x = (u64)__float_as_uint(w0) | ((u64)__float_as_uint(w1) << 32);
    v.y = (u64)__float_as_uint(w2) | ((u64)__float_as_uint(w3) << 32);
    reinterpret_cast<ulonglong2*>(g_Wt)[dst] = v;
}

// =====================================================================
// Kernel 1: GEMV — 8 tokens/warp, expert-pair packed accs, 1 wave.
// =====================================================================
__global__ void __launch_bounds__(256) gemv_kernel(const float* __restrict__ f,
                                                   const float* __restrict__ b) {
    const int lane = threadIdx.x & 31;
    const int wid  = threadIdx.x >> 5;
    const int t0   = (blockIdx.x * 8 + wid) * 8;

    const float4* F = reinterpret_cast<const float4*>(f + (size_t)t0 * ND);
    const ulonglong2* Wt = reinterpret_cast<const ulonglong2*>(g_Wt);

    u64 acc[8][8];
#pragma unroll
    for (int t = 0; t < 8; ++t)
#pragma unroll
        for (int p = 0; p < 8; ++p) acc[t][p] = 0ull;

    for (int i = 0; i < 16; ++i) {
        const int k4 = i * 32 + lane;
        float4 a[8];
#pragma unroll
        for (int t = 0; t < 8; ++t) a[t] = ldcs4(F + t * 512 + k4);
#pragma unroll
        for (int kk = 0; kk < 4; ++kk) {
            const int base = ((i * 4 + kk) * 4) * 32 + lane;
            const ulonglong2 wA = ldg2(Wt + base);
            const ulonglong2 wB = ldg2(Wt + base + 32);
            const ulonglong2 wC = ldg2(Wt + base + 64);
            const ulonglong2 wD = ldg2(Wt + base + 96);
#pragma unroll
            for (int t = 0; t < 8; ++t) {
                const float av = kk == 0 ? a[t].x : kk == 1 ? a[t].y
                               : kk == 2 ? a[t].z : a[t].w;
                const u64 s = splat2(av);
                acc[t][0] = ffma2(s, wA.x, acc[t][0]);
                acc[t][1] = ffma2(s, wA.y, acc[t][1]);
                acc[t][2] = ffma2(s, wB.x, acc[t][2]);
                acc[t][3] = ffma2(s, wB.y, acc[t][3]);
                acc[t][4] = ffma2(s, wC.x, acc[t][4]);
                acc[t][5] = ffma2(s, wC.y, acc[t][5]);
                acc[t][6] = ffma2(s, wD.x, acc[t][6]);
                acc[t][7] = ffma2(s, wD.y, acc[t][7]);
            }
        }
    }

    // reduce each (token, pair) across lanes; lane (t&3)*8+p keeps it
    u64 keep0 = 0, keep1 = 0;
#pragma unroll
    for (int t = 0; t < 8; ++t) {
#pragma unroll
        for (int p = 0; p < 8; ++p) {
            u64 v = acc[t][p];
#pragma unroll
            for (int o = 16; o; o >>= 1) v = addx2(v, shfl64_xor(v, o));
            if (lane == ((t & 3) * 8 + p)) { if (t < 4) keep0 = v; else keep1 = v; }
        }
    }

    const int p = lane & 7;       // expert pair (2p, 2p+1)
    const int g = lane >> 3;      // token group within warp
    const float b0 = __ldg(b + 2 * p), b1 = __ldg(b + 2 * p + 1);

#pragma unroll
    for (int pass = 0; pass < 2; ++pass) {
        const int t = t0 + pass * 4 + g;
        const u64 P = pass ? keep1 : keep0;
        const float f0 = __uint_as_float((unsigned)P) + b0;
        const float f1 = __uint_as_float((unsigned)(P >> 32)) + b1;

        // softmax over the 8-lane group (16 experts)
        float m = fmaxf(f0, f1);
#pragma unroll
        for (int o = 1; o < 8; o <<= 1) m = fmaxf(m, __shfl_xor_sync(FULLM, m, o));
        const float e0 = __expf(f0 - m), e1 = __expf(f1 - m);
        float s = e0 + e1;
#pragma unroll
        for (int o = 1; o < 8; o <<= 1) s += __shfl_xor_sync(FULLM, s, o);
        const float inv = __fdividef(1.f, s);
        g_probsT[(2 * p) * NT + t]     = e0 * inv;
        g_probsT[(2 * p + 1) * NT + t] = e1 * inv;

        // sortable keys (descending score, tie -> lower expert)
        unsigned u0 = __float_as_uint(f0), u1 = __float_as_uint(f1);
        u0 = (u0 & 0x80000000u) ? ~u0 : (u0 | 0x80000000u);
        u1 = (u1 & 0x80000000u) ? ~u1 : (u1 | 0x80000000u);
        const u64 k0 = ((u64)u0 << 4) | (u64)(15 - 2 * p);
        const u64 k1 = ((u64)u1 << 4) | (u64)(14 - 2 * p);
        int r0 = (k1 > k0), r1 = (k0 > k1);
#pragma unroll
        for (int j = 1; j < 8; ++j) {
            const u64 o0 = shfl64_xor(k0, j);
            const u64 o1 = shfl64_xor(k1, j);
            r0 += (o0 > k0) + (o1 > k0);
            r1 += (o0 > k1) + (o1 > k1);
        }
        u64 n = ((u64)(2 * p) << (4 * r0)) | ((u64)(2 * p + 1) << (4 * r1));
#pragma unroll
        for (int o = 1; o < 8; o <<= 1) n |= shfl64_xor(n, o);
        if (p == 0) g_prefs[t] = n;
    }
}

// =====================================================================
// Kernel 2: phased balanced assignment v7 (unchanged)
// =====================================================================
#define S_PREF_OFF 0
#define S_CH_OFF   65536
#define S_BLK_OFF  73728                 // [16][32] int
#define S_BPRE_OFF (73728 + 2048)        // [16][32] int
#define S_WCNT_OFF (73728 + 4096)        // [32][16] int
#define S_INT_OFF  (73728 + 6144)
#define SMEM_BYTES (73728 + 6144 + 128)
// s_int: [16] active, [17] start, [18] cut A, [19] cut B

__global__ void __launch_bounds__(1024) assign_kernel(float* __restrict__ out) {
    extern __shared__ unsigned char smem[];
    u64*      s_pref = (u64*)(smem + S_PREF_OFF);
    unsigned* s_ch   = (unsigned*)(smem + S_CH_OFF);   // 2048 words
    int*      s_blk  = (int*)(smem + S_BLK_OFF);
    int*      s_bpre = (int*)(smem + S_BPRE_OFF);
    int*      s_wcnt = (int*)(smem + S_WCNT_OFF);
    int*      s_int  = (int*)(smem + S_INT_OFF);

    const int tid  = threadIdx.x;
    const int lane = tid & 31;
    const int wid  = tid >> 5;
    const unsigned ltm = (1u << lane) - 1u;

    for (int i = tid; i < NT; i += 1024) s_pref[i] = g_prefs[i];
    if (tid == 0) { s_int[16] = 0xFFFF; s_int[17] = 0; s_int[18] = CINF; s_int[19] = CINF; }
    __syncthreads();

    // ---- build: warp wid counts+writes its 256-token block ----
    {
        u64 c0 = 0, c1 = 0, c2 = 0, c3 = 0;
#pragma unroll
        for (int i = 0; i < 2; ++i) {
            const int w = wid * 64 + i * 32 + lane;
            unsigned word = 0;
#pragma unroll
            for (int bb = 0; bb < 4; ++bb) {
                const int c = (int)(s_pref[w * 4 + bb] & 15);
                word |= (unsigned)c << (bb * 8);
                const u64 inc = 1ull << ((c & 3) << 4);
                if      ((c >> 2) == 0) c0 += inc;
                else if ((c >> 2) == 1) c1 += inc;
                else if ((c >> 2) == 2) c2 += inc;
                else                    c3 += inc;
            }
            s_ch[w] = word;
        }
#pragma unroll
        for (int o = 16; o; o >>= 1) {
            c0 += __shfl_xor_sync(FULLM, c0, o);
            c1 += __shfl_xor_sync(FULLM, c1, o);
            c2 += __shfl_xor_sync(FULLM, c2, o);
            c3 += __shfl_xor_sync(FULLM, c3, o);
        }
        if (lane < NE) {
            const u64 sel = (lane >> 2) == 0 ? c0 : (lane >> 2) == 1 ? c1
                          : (lane >> 2) == 2 ? c2 : c3;
            s_blk[lane * 32 + wid] = (int)((sel >> ((lane & 3) << 4)) & 0xFFFF);
        }
    }
    __syncthreads();

    // ---------------- phase loop ----------------
    for (int phase = 0; phase < NE; ++phase) {
        const int s = s_int[17];
        const int active  = s_int[16];
        const int cutslot = 18 + (phase & 1);

        if (wid < NE && ((active >> wid) & 1)) {
            const int e = wid;
            const unsigned splat = (unsigned)e * 0x01010101u;
            const int pb   = s >> 8;
            const int ws   = s >> 2;
            const int we_  = (pb + 1) * 64;
            const unsigned mfirst = 0xFFFFFFFFu << ((s & 3) * 8);

            const int i0 = ws + lane * 2;
            unsigned cm0 = 0, cm1 = 0;
            if (i0 < we_) {
                cm0 = __vcmpeq4(s_ch[i0], splat);
                if (i0 == ws) cm0 &= mfirst;
            }
            if (i0 + 1 < we_) cm1 = __vcmpeq4(s_ch[i0 + 1], splat);
            const int lcnt = (__popc(cm0) + __popc(cm1)) >> 3;
            const int ptotal = (int)__reduce_add_sync(FULLM, (unsigned)lcnt);

            const int bfull = s_blk[e * 32 + lane];
            int incl = bfull;
#pragma unroll
            for (int o = 1; o < 32; o <<= 1) {
                const int u = __shfl_up_sync(FULLM, incl, o);
                if (lane >= o) incl += u;
            }
            const int tot     = __shfl_sync(FULLM, incl, 31);
            const int pref_pb = __shfl_sync(FULLM, incl, pb);
            const int need    = CAP - (pref_pb - ptotal);
            const int live    = tot - pref_pb + ptotal;

            if (live >= need) {
                if (ptotal >= need) {
                    int linc = lcnt;
#pragma unroll
                    for (int o = 1; o < 32; o <<= 1) {
                        const int u = __shfl_up_sync(FULLM, linc, o);
                        if (lane >= o) linc += u;
                    }
                    const unsigned bal = __ballot_sync(FULLM, linc >= need);
                    const int cl = __ffs(bal) - 1;
                    if (lane == cl) {
                        int rem = need - (linc - lcnt);
                        int pos = -1;
#pragma unroll
                        for (int bb = 0; bb < 4 && pos < 0; ++bb)
                            if ((cm0 >> (bb * 8)) & 1u && --rem == 0) pos = i0 * 4 + bb;
#pragma unroll
                        for (int bb = 0; bb < 4 && pos < 0; ++bb)
                            if ((cm1 >> (bb * 8)) & 1u && --rem == 0) pos = (i0 + 1) * 4 + bb;
                        atomicMin(&s_int[cutslot], (pos << 4) | e);
                    }
                } else {
                    const int rem2 = need - ptotal;
                    const int minc = incl - pref_pb;
                    const unsigned bal = __ballot_sync(FULLM, lane > pb && minc >= rem2);
                    const int kc   = __ffs(bal) - 1;
                    const int excl = __shfl_sync(FULLM, incl - bfull, kc) - pref_pb;
                    const int rem3 = rem2 - excl;
                    const int j0 = kc * 64 + lane * 2;
                    const unsigned d0 = __vcmpeq4(s_ch[j0], splat);
                    const unsigned d1 = __vcmpeq4(s_ch[j0 + 1], splat);
                    const int lc = (__popc(d0) + __popc(d1)) >> 3;
                    int li = lc;
#pragma unroll
                    for (int o = 1; o < 32; o <<= 1) {
                        const int u = __shfl_up_sync(FULLM, li, o);
                        if (lane >= o) li += u;
                    }
                    const unsigned bal2 = __ballot_sync(FULLM, li >= rem3);
                    const int cl2 = __ffs(bal2) - 1;
                    if (lane == cl2) {
                        int rem = rem3 - (li - lc);
                        int pos = -1;
#pragma unroll
                        for (int bb = 0; bb < 4 && pos < 0; ++bb)
                            if ((d0 >> (bb * 8)) & 1u && --rem == 0) pos = j0 * 4 + bb;
#pragma unroll
                        for (int bb = 0; bb < 4 && pos < 0; ++bb)
                            if ((d1 >> (bb * 8)) & 1u && --rem == 0) pos = (j0 + 1) * 4 + bb;
                        atomicMin(&s_int[cutslot], (pos << 4) | e);
                    }
                }
            }
        }
        __syncthreads();                               // B1: cut final

        const int mv = s_int[cutslot];
        if (mv == CINF) {
            if (tid == 0) s_int[17] = NT;
            __syncthreads();
            continue;
        }
        const int pstar = mv >> 4, es = mv & 15;
        const int nactive = active & ~(1 << es);

        if (tid == 0) {
            s_int[16] = nactive;
            s_int[17] = pstar + 1;
            s_int[cutslot] = CINF;
        }
        {
            const int sn = pstar + 1;
            const int ws = sn >> 2;
            const unsigned splat = (unsigned)es * 0x01010101u;
            const unsigned mfirst = 0xFFFFFFFFu << ((sn & 3) * 8);
            for (int w = ws + tid; w < 2048; w += 1024) {
                unsigned word = s_ch[w];
                unsigned m = __vcmpeq4(word, splat);
                if (w == ws) m &= mfirst;
                if (m) {
                    const int blk = w >> 6;
                    int moved = 0;
                    do {
                        const int bb = (__ffs(m) - 1) >> 3;
                        m &= ~(0xFFu << (bb * 8));
                        u64 pw = s_pref[w * 4 + bb];
                        int c = (int)(pw & 15);
                        while (!((nactive >> c) & 1)) { pw >>= 4; c = (int)(pw & 15); }
                        word = (word & ~(0xFFu << (bb * 8))) | ((unsigned)c << (bb * 8));
                        atomicAdd(&s_blk[c * 32 + blk], 1);
                        ++moved;
                    } while (m);
                    atomicAdd(&s_blk[es * 32 + blk], -moved);
                    s_ch[w] = word;
                }
            }
        }
        __syncthreads();                               // B2: phase done
    }

    // ---------------- epilogue: rank via block prefixes + match_any ----------------
    if (wid < NE) {
        const int v = s_blk[wid * 32 + lane];
        int inc = v;
#pragma unroll
        for (int o = 1; o < 32; o <<= 1) {
            const int u = __shfl_up_sync(FULLM, inc, o);
            if (lane >= o) inc += u;
        }
        s_bpre[wid * 32 + lane] = wid * CAP + inc - v;
    }
    if (lane < NE) s_wcnt[wid * 16 + lane] = 0;
    __syncthreads();

    {
        const int base = wid * 256;
#pragma unroll
        for (int j = 0; j < 8; ++j) {
            const int t = base + j * 32 + lane;
            const int e = (int)((s_ch[t >> 2] >> ((t & 3) * 8)) & 0xFFu);
            const unsigned mask = __match_any_sync(FULLM, e);
            const int leader = __ffs(mask) - 1;
            int old = 0;
            if (lane == leader) old = atomicAdd(&s_wcnt[wid * 16 + e], __popc(mask));
            old = __shfl_sync(FULLM, old, leader);
            const int rank = s_bpre[e * 32 + wid] + old + __popc(mask & ltm);
            out[rank] = (float)t;
            out[NT + t] = g_probsT[e * NT + t];
        }
    }
}

// =====================================================================
extern "C" void kernel_launch(void* const* d_in, const int* in_sizes, int n_in,
                              void* d_out, int out_size) {
    const float* f = (const float*)d_in[0];   // features [8192, 2048] f32
    const float* W = (const float*)d_in[1];   // gate weight [16, 2048] f32
    const float* b = (const float*)d_in[2];   // bias [16] f32
    float* out = (float*)d_out;               // [8192] sort_by_expert ++ [8192] gathered

    wprep_kernel<<<32, 256>>>(W);
    gemv_kernel<<<NT / 64, 256>>>(f, b);

    cudaFuncSetAttribute(assign_kernel,
                         cudaFuncAttributeMaxDynamicSharedMemorySize, SMEM_BYTES);
    assign_kernel<<<1, 1024, SMEM_BYTES>>>(out);
}

// round 13
// speedup vs baseline: 1.7981x; 1.0402x over previous
#include <cuda_runtime.h>

#define NT 8192
#define ND 2048
#define NE 16
#define CAP 512
#define FULLM 0xFFFFFFFFu
#define CINF 0x7FFFFFFF

typedef unsigned long long u64;

__device__ float g_probsT[NE * NT];             // softmax probs, transposed [e][t]
__device__ u64   g_prefs[NT];                   // packed preference order (16 nibbles)
__device__ __align__(16) u64 g_Wt[ND * NE / 2]; // swizzled W, expert-pair packed
__device__ unsigned g_ch[NT / 4];               // final choices (bytes)
__device__ int      g_blk[NE * 32];             // final per-block expert counts

__device__ __forceinline__ u64 ffma2(u64 a, u64 b, u64 c) {
    u64 d;
    asm("fma.rn.f32x2 %0, %1, %2, %3;" : "=l"(d) : "l"(a), "l"(b), "l"(c));
    return d;
}
__device__ __forceinline__ u64 addx2(u64 a, u64 b) {
    u64 d;
    asm("add.rn.f32x2 %0, %1, %2;" : "=l"(d) : "l"(a), "l"(b));
    return d;
}
__device__ __forceinline__ u64 splat2(float x) {
    u64 r;
    asm("mov.b64 %0, {%1, %1};" : "=l"(r) : "f"(x));
    return r;
}
__device__ __forceinline__ u64 shfl64_xor(u64 v, int m) {
    unsigned lo = (unsigned)v, hi = (unsigned)(v >> 32);
    lo = __shfl_xor_sync(FULLM, lo, m);
    hi = __shfl_xor_sync(FULLM, hi, m);
    return (u64)lo | ((u64)hi << 32);
}
__device__ __forceinline__ float4 ldcs4(const float4* p) {
    float4 v;
    asm("ld.global.cs.v4.f32 {%0,%1,%2,%3}, [%4];"
        : "=f"(v.x), "=f"(v.y), "=f"(v.z), "=f"(v.w) : "l"(p));
    return v;
}
__device__ __forceinline__ ulonglong2 ldg2(const ulonglong2* p) {
    ulonglong2 v;
    asm("ld.global.nc.v2.u64 {%0, %1}, [%2];" : "=l"(v.x), "=l"(v.y) : "l"(p));
    return v;
}

// =====================================================================
// Kernel 0: one-time W swizzle (unchanged)
// =====================================================================
__global__ void wprep_kernel(const float* __restrict__ W) {
    const int idx = blockIdx.x * 256 + threadIdx.x;   // 0..8191 = k*4 + j
    const int k = idx >> 2, j = idx & 3;
    const int i = k >> 7, ln = (k >> 2) & 31, kk = k & 3;
    const int dst = ((i * 4 + kk) * 4 + j) * 32 + ln;
    const float w0 = W[(4 * j + 0) * ND + k];
    const float w1 = W[(4 * j + 1) * ND + k];
    const float w2 = W[(4 * j + 2) * ND + k];
    const float w3 = W[(4 * j + 3) * ND + k];
    ulonglong2 v;
    v.x = (u64)__float_as_uint(w0) | ((u64)__float_as_uint(w1) << 32);
    v.y = (u64)__float_as_uint(w2) | ((u64)__float_as_uint(w3) << 32);
    reinterpret_cast<ulonglong2*>(g_Wt)[dst] = v;
}

// =====================================================================
// Kernel 1: GEMV — 8 tokens/warp, expert-pair packed accs (unchanged)
// =====================================================================
__global__ void __launch_bounds__(256) gemv_kernel(const float* __restrict__ f,
                                                   const float* __restrict__ b) {
    const int lane = threadIdx.x & 31;
    const int wid  = threadIdx.x >> 5;
    const int t0   = (blockIdx.x * 8 + wid) * 8;

    const float4* F = reinterpret_cast<const float4*>(f + (size_t)t0 * ND);
    const ulonglong2* Wt = reinterpret_cast<const ulonglong2*>(g_Wt);

    u64 acc[8][8];
#pragma unroll
    for (int t = 0; t < 8; ++t)
#pragma unroll
        for (int p = 0; p < 8; ++p) acc[t][p] = 0ull;

    for (int i = 0; i < 16; ++i) {
        const int k4 = i * 32 + lane;
        float4 a[8];
#pragma unroll
        for (int t = 0; t < 8; ++t) a[t] = ldcs4(F + t * 512 + k4);
#pragma unroll
        for (int kk = 0; kk < 4; ++kk) {
            const int base = ((i * 4 + kk) * 4) * 32 + lane;
            const ulonglong2 wA = ldg2(Wt + base);
            const ulonglong2 wB = ldg2(Wt + base + 32);
            const ulonglong2 wC = ldg2(Wt + base + 64);
            const ulonglong2 wD = ldg2(Wt + base + 96);
#pragma unroll
            for (int t = 0; t < 8; ++t) {
                const float av = kk == 0 ? a[t].x : kk == 1 ? a[t].y
                               : kk == 2 ? a[t].z : a[t].w;
                const u64 s = splat2(av);
                acc[t][0] = ffma2(s, wA.x, acc[t][0]);
                acc[t][1] = ffma2(s, wA.y, acc[t][1]);
                acc[t][2] = ffma2(s, wB.x, acc[t][2]);
                acc[t][3] = ffma2(s, wB.y, acc[t][3]);
                acc[t][4] = ffma2(s, wC.x, acc[t][4]);
                acc[t][5] = ffma2(s, wC.y, acc[t][5]);
                acc[t][6] = ffma2(s, wD.x, acc[t][6]);
                acc[t][7] = ffma2(s, wD.y, acc[t][7]);
            }
        }
    }

    u64 keep0 = 0, keep1 = 0;
#pragma unroll
    for (int t = 0; t < 8; ++t) {
#pragma unroll
        for (int p = 0; p < 8; ++p) {
            u64 v = acc[t][p];
#pragma unroll
            for (int o = 16; o; o >>= 1) v = addx2(v, shfl64_xor(v, o));
            if (lane == ((t & 3) * 8 + p)) { if (t < 4) keep0 = v; else keep1 = v; }
        }
    }

    const int p = lane & 7;
    const int g = lane >> 3;
    const float b0 = __ldg(b + 2 * p), b1 = __ldg(b + 2 * p + 1);

#pragma unroll
    for (int pass = 0; pass < 2; ++pass) {
        const int t = t0 + pass * 4 + g;
        const u64 P = pass ? keep1 : keep0;
        const float f0 = __uint_as_float((unsigned)P) + b0;
        const float f1 = __uint_as_float((unsigned)(P >> 32)) + b1;

        float m = fmaxf(f0, f1);
#pragma unroll
        for (int o = 1; o < 8; o <<= 1) m = fmaxf(m, __shfl_xor_sync(FULLM, m, o));
        const float e0 = __expf(f0 - m), e1 = __expf(f1 - m);
        float s = e0 + e1;
#pragma unroll
        for (int o = 1; o < 8; o <<= 1) s += __shfl_xor_sync(FULLM, s, o);
        const float inv = __fdividef(1.f, s);
        g_probsT[(2 * p) * NT + t]     = e0 * inv;
        g_probsT[(2 * p + 1) * NT + t] = e1 * inv;

        unsigned u0 = __float_as_uint(f0), u1 = __float_as_uint(f1);
        u0 = (u0 & 0x80000000u) ? ~u0 : (u0 | 0x80000000u);
        u1 = (u1 & 0x80000000u) ? ~u1 : (u1 | 0x80000000u);
        const u64 k0 = ((u64)u0 << 4) | (u64)(15 - 2 * p);
        const u64 k1 = ((u64)u1 << 4) | (u64)(14 - 2 * p);
        int r0 = (k1 > k0), r1 = (k0 > k1);
#pragma unroll
        for (int j = 1; j < 8; ++j) {
            const u64 o0 = shfl64_xor(k0, j);
            const u64 o1 = shfl64_xor(k1, j);
            r0 += (o0 > k0) + (o1 > k0);
            r1 += (o0 > k1) + (o1 > k1);
        }
        u64 n = ((u64)(2 * p) << (4 * r0)) | ((u64)(2 * p + 1) << (4 * r1));
#pragma unroll
        for (int o = 1; o < 8; o <<= 1) n |= shfl64_xor(n, o);
        if (p == 0) g_prefs[t] = n;
    }
}

// =====================================================================
// Kernel 2: phased balanced assignment. Grid padded to 148 (throttle
// workaround); epilogue moved out — dumps g_ch / g_blk at the end.
// =====================================================================
#define S_PREF_OFF 0
#define S_CH_OFF   65536
#define S_BLK_OFF  73728                 // [16][32] int
#define S_INT_OFF  (73728 + 2048)
#define SMEM_BYTES (73728 + 2048 + 128)
// s_int: [16] active, [17] start, [18] cut A, [19] cut B

__global__ void __launch_bounds__(1024) assign_kernel() {
    if (blockIdx.x != 0) return;          // grid padded to defeat 1-CTA throttle
    extern __shared__ unsigned char smem[];
    u64*      s_pref = (u64*)(smem + S_PREF_OFF);
    unsigned* s_ch   = (unsigned*)(smem + S_CH_OFF);   // 2048 words
    int*      s_blk  = (int*)(smem + S_BLK_OFF);
    int*      s_int  = (int*)(smem + S_INT_OFF);

    const int tid  = threadIdx.x;
    const int lane = tid & 31;
    const int wid  = tid >> 5;

    for (int i = tid; i < NT; i += 1024) s_pref[i] = g_prefs[i];
    if (tid == 0) { s_int[16] = 0xFFFF; s_int[17] = 0; s_int[18] = CINF; s_int[19] = CINF; }
    __syncthreads();

    // ---- build: warp wid counts+writes its 256-token block ----
    {
        u64 c0 = 0, c1 = 0, c2 = 0, c3 = 0;
#pragma unroll
        for (int i = 0; i < 2; ++i) {
            const int w = wid * 64 + i * 32 + lane;
            unsigned word = 0;
#pragma unroll
            for (int bb = 0; bb < 4; ++bb) {
                const int c = (int)(s_pref[w * 4 + bb] & 15);
                word |= (unsigned)c << (bb * 8);
                const u64 inc = 1ull << ((c & 3) << 4);
                if      ((c >> 2) == 0) c0 += inc;
                else if ((c >> 2) == 1) c1 += inc;
                else if ((c >> 2) == 2) c2 += inc;
                else                    c3 += inc;
            }
            s_ch[w] = word;
        }
#pragma unroll
        for (int o = 16; o; o >>= 1) {
            c0 += __shfl_xor_sync(FULLM, c0, o);
            c1 += __shfl_xor_sync(FULLM, c1, o);
            c2 += __shfl_xor_sync(FULLM, c2, o);
            c3 += __shfl_xor_sync(FULLM, c3, o);
        }
        if (lane < NE) {
            const u64 sel = (lane >> 2) == 0 ? c0 : (lane >> 2) == 1 ? c1
                          : (lane >> 2) == 2 ? c2 : c3;
            s_blk[lane * 32 + wid] = (int)((sel >> ((lane & 3) << 4)) & 0xFFFF);
        }
    }
    __syncthreads();

    // ---------------- phase loop ----------------
    for (int phase = 0; phase < NE; ++phase) {
        const int s = s_int[17];
        const int active  = s_int[16];
        const int cutslot = 18 + (phase & 1);

        if (wid < NE && ((active >> wid) & 1)) {
            const int e = wid;
            const unsigned splat = (unsigned)e * 0x01010101u;
            const int pb   = s >> 8;
            const int ws   = s >> 2;
            const int we_  = (pb + 1) * 64;
            const unsigned mfirst = 0xFFFFFFFFu << ((s & 3) * 8);

            const int i0 = ws + lane * 2;
            unsigned cm0 = 0, cm1 = 0;
            if (i0 < we_) {
                cm0 = __vcmpeq4(s_ch[i0], splat);
                if (i0 == ws) cm0 &= mfirst;
            }
            if (i0 + 1 < we_) cm1 = __vcmpeq4(s_ch[i0 + 1], splat);
            const int lcnt = (__popc(cm0) + __popc(cm1)) >> 3;
            const int ptotal = (int)__reduce_add_sync(FULLM, (unsigned)lcnt);

            const int bfull = s_blk[e * 32 + lane];
            int incl = bfull;
#pragma unroll
            for (int o = 1; o < 32; o <<= 1) {
                const int u = __shfl_up_sync(FULLM, incl, o);
                if (lane >= o) incl += u;
            }
            const int tot     = __shfl_sync(FULLM, incl, 31);
            const int pref_pb = __shfl_sync(FULLM, incl, pb);
            const int need    = CAP - (pref_pb - ptotal);
            const int live    = tot - pref_pb + ptotal;

            if (live >= need) {
                if (ptotal >= need) {
                    int linc = lcnt;
#pragma unroll
                    for (int o = 1; o < 32; o <<= 1) {
                        const int u = __shfl_up_sync(FULLM, linc, o);
                        if (lane >= o) linc += u;
                    }
                    const unsigned bal = __ballot_sync(FULLM, linc >= need);
                    const int cl = __ffs(bal) - 1;
                    if (lane == cl) {
                        int rem = need - (linc - lcnt);
                        int pos = -1;
#pragma unroll
                        for (int bb = 0; bb < 4 && pos < 0; ++bb)
                            if ((cm0 >> (bb * 8)) & 1u && --rem == 0) pos = i0 * 4 + bb;
#pragma unroll
                        for (int bb = 0; bb < 4 && pos < 0; ++bb)
                            if ((cm1 >> (bb * 8)) & 1u && --rem == 0) pos = (i0 + 1) * 4 + bb;
                        atomicMin(&s_int[cutslot], (pos << 4) | e);
                    }
                } else {
                    const int rem2 = need - ptotal;
                    const int minc = incl - pref_pb;
                    const unsigned bal = __ballot_sync(FULLM, lane > pb && minc >= rem2);
                    const int kc   = __ffs(bal) - 1;
                    const int excl = __shfl_sync(FULLM, incl - bfull, kc) - pref_pb;
                    const int rem3 = rem2 - excl;
                    const int j0 = kc * 64 + lane * 2;
                    const unsigned d0 = __vcmpeq4(s_ch[j0], splat);
                    const unsigned d1 = __vcmpeq4(s_ch[j0 + 1], splat);
                    const int lc = (__popc(d0) + __popc(d1)) >> 3;
                    int li = lc;
#pragma unroll
                    for (int o = 1; o < 32; o <<= 1) {
                        const int u = __shfl_up_sync(FULLM, li, o);
                        if (lane >= o) li += u;
                    }
                    const unsigned bal2 = __ballot_sync(FULLM, li >= rem3);
                    const int cl2 = __ffs(bal2) - 1;
                    if (lane == cl2) {
                        int rem = rem3 - (li - lc);
                        int pos = -1;
#pragma unroll
                        for (int bb = 0; bb < 4 && pos < 0; ++bb)
                            if ((d0 >> (bb * 8)) & 1u && --rem == 0) pos = j0 * 4 + bb;
#pragma unroll
                        for (int bb = 0; bb < 4 && pos < 0; ++bb)
                            if ((d1 >> (bb * 8)) & 1u && --rem == 0) pos = (j0 + 1) * 4 + bb;
                        atomicMin(&s_int[cutslot], (pos << 4) | e);
                    }
                }
            }
        }
        __syncthreads();                               // B1: cut final

        const int mv = s_int[cutslot];
        if (mv == CINF) {
            if (tid == 0) s_int[17] = NT;
            __syncthreads();
            continue;
        }
        const int pstar = mv >> 4, es = mv & 15;
        const int nactive = active & ~(1 << es);

        if (tid == 0) {
            s_int[16] = nactive;
            s_int[17] = pstar + 1;
            s_int[cutslot] = CINF;
        }
        {
            const int sn = pstar + 1;
            const int ws = sn >> 2;
            const unsigned splat = (unsigned)es * 0x01010101u;
            const unsigned mfirst = 0xFFFFFFFFu << ((sn & 3) * 8);
            for (int w = ws + tid; w < 2048; w += 1024) {
                unsigned word = s_ch[w];
                unsigned m = __vcmpeq4(word, splat);
                if (w == ws) m &= mfirst;
                if (m) {
                    const int blk = w >> 6;
                    int moved = 0;
                    do {
                        const int bb = (__ffs(m) - 1) >> 3;
                        m &= ~(0xFFu << (bb * 8));
                        u64 pw = s_pref[w * 4 + bb];
                        int c = (int)(pw & 15);
                        while (!((nactive >> c) & 1)) { pw >>= 4; c = (int)(pw & 15); }
                        word = (word & ~(0xFFu << (bb * 8))) | ((unsigned)c << (bb * 8));
                        atomicAdd(&s_blk[c * 32 + blk], 1);
                        ++moved;
                    } while (m);
                    atomicAdd(&s_blk[es * 32 + blk], -moved);
                    s_ch[w] = word;
                }
            }
        }
        __syncthreads();                               // B2: phase done
    }

    // ---- dump state for the wide epilogue kernel ----
    for (int i = tid; i < NT / 4; i += 1024) g_ch[i] = s_ch[i];
    if (tid < NE * 32) g_blk[tid] = s_blk[tid];
}

// =====================================================================
// Kernel 3: wide epilogue — ranking + output writes on 32 blocks.
// Block b owns tokens [b*256, (b+1)*256); one token per thread.
// =====================================================================
__global__ void __launch_bounds__(256) epilogue_kernel(float* __restrict__ out) {
    __shared__ int s_base[NE];        // expert base for this block
    __shared__ int s_cnt[8][NE];      // per-warp per-expert counts -> prefixes
    const int b = blockIdx.x, tid = threadIdx.x;
    const int lane = tid & 31, wid = tid >> 5;
    const unsigned ltm = (1u << lane) - 1u;

    if (tid < NE) {
        int acc = tid * CAP;
        for (int k = 0; k < b; ++k) acc += g_blk[tid * 32 + k];
        s_base[tid] = acc;
    }
    if (tid < 8 * NE) s_cnt[tid >> 4][tid & 15] = 0;
    __syncthreads();

    const int t = b * 256 + tid;
    const int e = (int)((g_ch[t >> 2] >> ((t & 3) * 8)) & 0xFFu);
    const unsigned mask = __match_any_sync(FULLM, e);
    const int leader = __ffs(mask) - 1;
    if (lane == leader) s_cnt[wid][e] = __popc(mask);
    __syncthreads();

    if (tid < NE) {                   // exclusive prefix across the 8 warps
        int acc = 0;
#pragma unroll
        for (int w = 0; w < 8; ++w) {
            const int v = s_cnt[w][tid];
            s_cnt[w][tid] = acc;
            acc += v;
        }
    }
    __syncthreads();

    const int rank = s_base[e] + s_cnt[wid][e] + __popc(mask & ltm);
    out[rank] = (float)t;
    out[NT + t] = g_probsT[e * NT + t];
}

// =====================================================================
extern "C" void kernel_launch(void* const* d_in, const int* in_sizes, int n_in,
                              void* d_out, int out_size) {
    const float* f = (const float*)d_in[0];   // features [8192, 2048] f32
    const float* W = (const float*)d_in[1];   // gate weight [16, 2048] f32
    const float* b = (const float*)d_in[2];   // bias [16] f32
    float* out = (float*)d_out;               // [8192] sort_by_expert ++ [8192] gathered

    wprep_kernel<<<32, 256>>>(W);
    gemv_kernel<<<NT / 64, 256>>>(f, b);

    cudaFuncSetAttribute(assign_kernel,
                         cudaFuncAttributeMaxDynamicSharedMemorySize, SMEM_BYTES);
    assign_kernel<<<148, 1024, SMEM_BYTES>>>();

    epilogue_kernel<<<NT / 256, 256>>>(out);
}

// round 14
// speedup vs baseline: 1.8497x; 1.0287x over previous
#include <cuda_runtime.h>

#define NT 8192
#define ND 2048
#define NE 16
#define CAP 512
#define FULLM 0xFFFFFFFFu
#define CINF 0x7FFFFFFF

typedef unsigned long long u64;

__device__ float g_probsT[NE * NT];             // softmax probs, transposed [e][t]
__device__ u64   g_prefs[NT];                   // packed preference order (16 nibbles)
__device__ __align__(16) u64 g_Wt[ND * NE / 2]; // swizzled W, expert-pair packed
__device__ unsigned g_ch[NT / 4];               // final choices (bytes)
__device__ int      g_bpre[NE * 32];            // global out-base per (expert, block)

__device__ __forceinline__ u64 ffma2(u64 a, u64 b, u64 c) {
    u64 d;
    asm("fma.rn.f32x2 %0, %1, %2, %3;" : "=l"(d) : "l"(a), "l"(b), "l"(c));
    return d;
}
__device__ __forceinline__ u64 addx2(u64 a, u64 b) {
    u64 d;
    asm("add.rn.f32x2 %0, %1, %2;" : "=l"(d) : "l"(a), "l"(b));
    return d;
}
__device__ __forceinline__ u64 splat2(float x) {
    u64 r;
    asm("mov.b64 %0, {%1, %1};" : "=l"(r) : "f"(x));
    return r;
}
__device__ __forceinline__ u64 shfl64_xor(u64 v, int m) {
    unsigned lo = (unsigned)v, hi = (unsigned)(v >> 32);
    lo = __shfl_xor_sync(FULLM, lo, m);
    hi = __shfl_xor_sync(FULLM, hi, m);
    return (u64)lo | ((u64)hi << 32);
}
__device__ __forceinline__ float4 ldcs4(const float4* p) {
    float4 v;
    asm("ld.global.cs.v4.f32 {%0,%1,%2,%3}, [%4];"
        : "=f"(v.x), "=f"(v.y), "=f"(v.z), "=f"(v.w) : "l"(p));
    return v;
}
__device__ __forceinline__ ulonglong2 ldg2(const ulonglong2* p) {
    ulonglong2 v;
    asm("ld.global.nc.v2.u64 {%0, %1}, [%2];" : "=l"(v.x), "=l"(v.y) : "l"(p));
    return v;
}

// =====================================================================
// Kernel 0: one-time W swizzle (unchanged)
// =====================================================================
__global__ void wprep_kernel(const float* __restrict__ W) {
    const int idx = blockIdx.x * 256 + threadIdx.x;   // 0..8191 = k*4 + j
    const int k = idx >> 2, j = idx & 3;
    const int i = k >> 7, ln = (k >> 2) & 31, kk = k & 3;
    const int dst = ((i * 4 + kk) * 4 + j) * 32 + ln;
    const float w0 = W[(4 * j + 0) * ND + k];
    const float w1 = W[(4 * j + 1) * ND + k];
    const float w2 = W[(4 * j + 2) * ND + k];
    const float w3 = W[(4 * j + 3) * ND + k];
    ulonglong2 v;
    v.x = (u64)__float_as_uint(w0) | ((u64)__float_as_uint(w1) << 32);
    v.y = (u64)__float_as_uint(w2) | ((u64)__float_as_uint(w3) << 32);
    reinterpret_cast<ulonglong2*>(g_Wt)[dst] = v;
}

// =====================================================================
// Kernel 1: GEMV — 8 tokens/warp, expert-pair packed accs (unchanged)
// =====================================================================
__global__ void __launch_bounds__(256) gemv_kernel(const float* __restrict__ f,
                                                   const float* __restrict__ b) {
    const int lane = threadIdx.x & 31;
    const int wid  = threadIdx.x >> 5;
    const int t0   = (blockIdx.x * 8 + wid) * 8;

    const float4* F = reinterpret_cast<const float4*>(f + (size_t)t0 * ND);
    const ulonglong2* Wt = reinterpret_cast<const ulonglong2*>(g_Wt);

    u64 acc[8][8];
#pragma unroll
    for (int t = 0; t < 8; ++t)
#pragma unroll
        for (int p = 0; p < 8; ++p) acc[t][p] = 0ull;

    for (int i = 0; i < 16; ++i) {
        const int k4 = i * 32 + lane;
        float4 a[8];
#pragma unroll
        for (int t = 0; t < 8; ++t) a[t] = ldcs4(F + t * 512 + k4);
#pragma unroll
        for (int kk = 0; kk < 4; ++kk) {
            const int base = ((i * 4 + kk) * 4) * 32 + lane;
            const ulonglong2 wA = ldg2(Wt + base);
            const ulonglong2 wB = ldg2(Wt + base + 32);
            const ulonglong2 wC = ldg2(Wt + base + 64);
            const ulonglong2 wD = ldg2(Wt + base + 96);
#pragma unroll
            for (int t = 0; t < 8; ++t) {
                const float av = kk == 0 ? a[t].x : kk == 1 ? a[t].y
                               : kk == 2 ? a[t].z : a[t].w;
                const u64 s = splat2(av);
                acc[t][0] = ffma2(s, wA.x, acc[t][0]);
                acc[t][1] = ffma2(s, wA.y, acc[t][1]);
                acc[t][2] = ffma2(s, wB.x, acc[t][2]);
                acc[t][3] = ffma2(s, wB.y, acc[t][3]);
                acc[t][4] = ffma2(s, wC.x, acc[t][4]);
                acc[t][5] = ffma2(s, wC.y, acc[t][5]);
                acc[t][6] = ffma2(s, wD.x, acc[t][6]);
                acc[t][7] = ffma2(s, wD.y, acc[t][7]);
            }
        }
    }

    u64 keep0 = 0, keep1 = 0;
#pragma unroll
    for (int t = 0; t < 8; ++t) {
#pragma unroll
        for (int p = 0; p < 8; ++p) {
            u64 v = acc[t][p];
#pragma unroll
            for (int o = 16; o; o >>= 1) v = addx2(v, shfl64_xor(v, o));
            if (lane == ((t & 3) * 8 + p)) { if (t < 4) keep0 = v; else keep1 = v; }
        }
    }

    const int p = lane & 7;
    const int g = lane >> 3;
    const float b0 = __ldg(b + 2 * p), b1 = __ldg(b + 2 * p + 1);

#pragma unroll
    for (int pass = 0; pass < 2; ++pass) {
        const int t = t0 + pass * 4 + g;
        const u64 P = pass ? keep1 : keep0;
        const float f0 = __uint_as_float((unsigned)P) + b0;
        const float f1 = __uint_as_float((unsigned)(P >> 32)) + b1;

        float m = fmaxf(f0, f1);
#pragma unroll
        for (int o = 1; o < 8; o <<= 1) m = fmaxf(m, __shfl_xor_sync(FULLM, m, o));
        const float e0 = __expf(f0 - m), e1 = __expf(f1 - m);
        float s = e0 + e1;
#pragma unroll
        for (int o = 1; o < 8; o <<= 1) s += __shfl_xor_sync(FULLM, s, o);
        const float inv = __fdividef(1.f, s);
        g_probsT[(2 * p) * NT + t]     = e0 * inv;
        g_probsT[(2 * p + 1) * NT + t] = e1 * inv;

        unsigned u0 = __float_as_uint(f0), u1 = __float_as_uint(f1);
        u0 = (u0 & 0x80000000u) ? ~u0 : (u0 | 0x80000000u);
        u1 = (u1 & 0x80000000u) ? ~u1 : (u1 | 0x80000000u);
        const u64 k0 = ((u64)u0 << 4) | (u64)(15 - 2 * p);
        const u64 k1 = ((u64)u1 << 4) | (u64)(14 - 2 * p);
        int r0 = (k1 > k0), r1 = (k0 > k1);
#pragma unroll
        for (int j = 1; j < 8; ++j) {
            const u64 o0 = shfl64_xor(k0, j);
            const u64 o1 = shfl64_xor(k1, j);
            r0 += (o0 > k0) + (o1 > k0);
            r1 += (o0 > k1) + (o1 > k1);
        }
        u64 n = ((u64)(2 * p) << (4 * r0)) | ((u64)(2 * p + 1) << (4 * r1));
#pragma unroll
        for (int o = 1; o < 8; o <<= 1) n |= shfl64_xor(n, o);
        if (p == 0) g_prefs[t] = n;
    }
}

// =====================================================================
// Kernel 2: phased balanced assignment. Dumps g_ch + PREFIXED g_bpre.
// =====================================================================
#define S_PREF_OFF 0
#define S_CH_OFF   65536
#define S_BLK_OFF  73728                 // [16][32] int
#define S_INT_OFF  (73728 + 2048)
#define SMEM_BYTES (73728 + 2048 + 128)
// s_int: [16] active, [17] start, [18] cut A, [19] cut B

__global__ void __launch_bounds__(1024) assign_kernel() {
    if (blockIdx.x != 0) return;          // grid padded to defeat 1-CTA throttle
    extern __shared__ unsigned char smem[];
    u64*      s_pref = (u64*)(smem + S_PREF_OFF);
    unsigned* s_ch   = (unsigned*)(smem + S_CH_OFF);   // 2048 words
    int*      s_blk  = (int*)(smem + S_BLK_OFF);
    int*      s_int  = (int*)(smem + S_INT_OFF);

    const int tid  = threadIdx.x;
    const int lane = tid & 31;
    const int wid  = tid >> 5;

    for (int i = tid; i < NT; i += 1024) s_pref[i] = g_prefs[i];
    if (tid == 0) { s_int[16] = 0xFFFF; s_int[17] = 0; s_int[18] = CINF; s_int[19] = CINF; }
    __syncthreads();

    // ---- build: warp wid counts+writes its 256-token block ----
    {
        u64 c0 = 0, c1 = 0, c2 = 0, c3 = 0;
#pragma unroll
        for (int i = 0; i < 2; ++i) {
            const int w = wid * 64 + i * 32 + lane;
            unsigned word = 0;
#pragma unroll
            for (int bb = 0; bb < 4; ++bb) {
                const int c = (int)(s_pref[w * 4 + bb] & 15);
                word |= (unsigned)c << (bb * 8);
                const u64 inc = 1ull << ((c & 3) << 4);
                if      ((c >> 2) == 0) c0 += inc;
                else if ((c >> 2) == 1) c1 += inc;
                else if ((c >> 2) == 2) c2 += inc;
                else                    c3 += inc;
            }
            s_ch[w] = word;
        }
#pragma unroll
        for (int o = 16; o; o >>= 1) {
            c0 += __shfl_xor_sync(FULLM, c0, o);
            c1 += __shfl_xor_sync(FULLM, c1, o);
            c2 += __shfl_xor_sync(FULLM, c2, o);
            c3 += __shfl_xor_sync(FULLM, c3, o);
        }
        if (lane < NE) {
            const u64 sel = (lane >> 2) == 0 ? c0 : (lane >> 2) == 1 ? c1
                          : (lane >> 2) == 2 ? c2 : c3;
            s_blk[lane * 32 + wid] = (int)((sel >> ((lane & 3) << 4)) & 0xFFFF);
        }
    }
    __syncthreads();

    // ---------------- phase loop ----------------
    for (int phase = 0; phase < NE; ++phase) {
        const int s = s_int[17];
        const int active  = s_int[16];
        const int cutslot = 18 + (phase & 1);

        if (wid < NE && ((active >> wid) & 1)) {
            const int e = wid;
            const unsigned splat = (unsigned)e * 0x01010101u;
            const int pb   = s >> 8;
            const int ws   = s >> 2;
            const int we_  = (pb + 1) * 64;
            const unsigned mfirst = 0xFFFFFFFFu << ((s & 3) * 8);

            const int i0 = ws + lane * 2;
            unsigned cm0 = 0, cm1 = 0;
            if (i0 < we_) {
                cm0 = __vcmpeq4(s_ch[i0], splat);
                if (i0 == ws) cm0 &= mfirst;
            }
            if (i0 + 1 < we_) cm1 = __vcmpeq4(s_ch[i0 + 1], splat);
            const int lcnt = (__popc(cm0) + __popc(cm1)) >> 3;
            const int ptotal = (int)__reduce_add_sync(FULLM, (unsigned)lcnt);

            const int bfull = s_blk[e * 32 + lane];
            int incl = bfull;
#pragma unroll
            for (int o = 1; o < 32; o <<= 1) {
                const int u = __shfl_up_sync(FULLM, incl, o);
                if (lane >= o) incl += u;
            }
            const int tot     = __shfl_sync(FULLM, incl, 31);
            const int pref_pb = __shfl_sync(FULLM, incl, pb);
            const int need    = CAP - (pref_pb - ptotal);
            const int live    = tot - pref_pb + ptotal;

            if (live >= need) {
                if (ptotal >= need) {
                    int linc = lcnt;
#pragma unroll
                    for (int o = 1; o < 32; o <<= 1) {
                        const int u = __shfl_up_sync(FULLM, linc, o);
                        if (lane >= o) linc += u;
                    }
                    const unsigned bal = __ballot_sync(FULLM, linc >= need);
                    const int cl = __ffs(bal) - 1;
                    if (lane == cl) {
                        int rem = need - (linc - lcnt);
                        int pos = -1;
#pragma unroll
                        for (int bb = 0; bb < 4 && pos < 0; ++bb)
                            if ((cm0 >> (bb * 8)) & 1u && --rem == 0) pos = i0 * 4 + bb;
#pragma unroll
                        for (int bb = 0; bb < 4 && pos < 0; ++bb)
                            if ((cm1 >> (bb * 8)) & 1u && --rem == 0) pos = (i0 + 1) * 4 + bb;
                        atomicMin(&s_int[cutslot], (pos << 4) | e);
                    }
                } else {
                    const int rem2 = need - ptotal;
                    const int minc = incl - pref_pb;
                    const unsigned bal = __ballot_sync(FULLM, lane > pb && minc >= rem2);
                    const int kc   = __ffs(bal) - 1;
                    const int excl = __shfl_sync(FULLM, incl - bfull, kc) - pref_pb;
                    const int rem3 = rem2 - excl;
                    const int j0 = kc * 64 + lane * 2;
                    const unsigned d0 = __vcmpeq4(s_ch[j0], splat);
                    const unsigned d1 = __vcmpeq4(s_ch[j0 + 1], splat);
                    const int lc = (__popc(d0) + __popc(d1)) >> 3;
                    int li = lc;
#pragma unroll
                    for (int o = 1; o < 32; o <<= 1) {
                        const int u = __shfl_up_sync(FULLM, li, o);
                        if (lane >= o) li += u;
                    }
                    const unsigned bal2 = __ballot_sync(FULLM, li >= rem3);
                    const int cl2 = __ffs(bal2) - 1;
                    if (lane == cl2) {
                        int rem = rem3 - (li - lc);
                        int pos = -1;
#pragma unroll
                        for (int bb = 0; bb < 4 && pos < 0; ++bb)
                            if ((d0 >> (bb * 8)) & 1u && --rem == 0) pos = j0 * 4 + bb;
#pragma unroll
                        for (int bb = 0; bb < 4 && pos < 0; ++bb)
                            if ((d1 >> (bb * 8)) & 1u && --rem == 0) pos = (j0 + 1) * 4 + bb;
                        atomicMin(&s_int[cutslot], (pos << 4) | e);
                    }
                }
            }
        }
        __syncthreads();                               // B1: cut final

        const int mv = s_int[cutslot];
        if (mv == CINF) {
            if (tid == 0) s_int[17] = NT;
            __syncthreads();
            continue;
        }
        const int pstar = mv >> 4, es = mv & 15;
        const int nactive = active & ~(1 << es);

        if (tid == 0) {
            s_int[16] = nactive;
            s_int[17] = pstar + 1;
            s_int[cutslot] = CINF;
        }
        {
            const int sn = pstar + 1;
            const int ws = sn >> 2;
            const unsigned splat = (unsigned)es * 0x01010101u;
            const unsigned mfirst = 0xFFFFFFFFu << ((sn & 3) * 8);
            for (int w = ws + tid; w < 2048; w += 1024) {
                unsigned word = s_ch[w];
                unsigned m = __vcmpeq4(word, splat);
                if (w == ws) m &= mfirst;
                if (m) {
                    const int blk = w >> 6;
                    int moved = 0;
                    do {
                        const int bb = (__ffs(m) - 1) >> 3;
                        m &= ~(0xFFu << (bb * 8));
                        u64 pw = s_pref[w * 4 + bb];
                        int c = (int)(pw & 15);
                        while (!((nactive >> c) & 1)) { pw >>= 4; c = (int)(pw & 15); }
                        word = (word & ~(0xFFu << (bb * 8))) | ((unsigned)c << (bb * 8));
                        atomicAdd(&s_blk[c * 32 + blk], 1);
                        ++moved;
                    } while (m);
                    atomicAdd(&s_blk[es * 32 + blk], -moved);
                    s_ch[w] = word;
                }
            }
        }
        __syncthreads();                               // B2: phase done
    }

    // ---- dump choices + per-(expert, block) OUTPUT BASES (prefixed) ----
    for (int i = tid; i < NT / 4; i += 1024) g_ch[i] = s_ch[i];
    if (wid < NE) {
        const int v = s_blk[wid * 32 + lane];
        int incl = v;
#pragma unroll
        for (int o = 1; o < 32; o <<= 1) {
            const int u = __shfl_up_sync(FULLM, incl, o);
            if (lane >= o) incl += u;
        }
        g_bpre[wid * 32 + lane] = wid * CAP + incl - v;   // exclusive prefix
    }
}

// =====================================================================
// Kernel 3: wide epilogue — block b reads its 16 bases directly.
// =====================================================================
__global__ void __launch_bounds__(256) epilogue_kernel(float* __restrict__ out) {
    __shared__ int s_base[NE];        // expert base for this block (prefixed)
    __shared__ int s_cnt[8][NE];      // per-warp per-expert counts -> prefixes
    const int b = blockIdx.x, tid = threadIdx.x;
    const int lane = tid & 31, wid = tid >> 5;
    const unsigned ltm = (1u << lane) - 1u;

    if (tid < NE) s_base[tid] = g_bpre[tid * 32 + b];
    if (tid < 8 * NE) s_cnt[tid >> 4][tid & 15] = 0;
    __syncthreads();

    const int t = b * 256 + tid;
    const int e = (int)((g_ch[t >> 2] >> ((t & 3) * 8)) & 0xFFu);
    const unsigned mask = __match_any_sync(FULLM, e);
    const int leader = __ffs(mask) - 1;
    if (lane == leader) s_cnt[wid][e] = __popc(mask);
    __syncthreads();

    if (tid < NE) {                   // exclusive prefix across the 8 warps
        int acc = 0;
#pragma unroll
        for (int w = 0; w < 8; ++w) {
            const int v = s_cnt[w][tid];
            s_cnt[w][tid] = acc;
            acc += v;
        }
    }
    __syncthreads();

    const int rank = s_base[e] + s_cnt[wid][e] + __popc(mask & ltm);
    out[rank] = (float)t;
    out[NT + t] = g_probsT[e * NT + t];
}

// =====================================================================
extern "C" void kernel_launch(void* const* d_in, const int* in_sizes, int n_in,
                              void* d_out, int out_size) {
    const float* f = (const float*)d_in[0];   // features [8192, 2048] f32
    const float* W = (const float*)d_in[1];   // gate weight [16, 2048] f32
    const float* b = (const float*)d_in[2];   // bias [16] f32
    float* out = (float*)d_out;               // [8192] sort_by_expert ++ [8192] gathered

    wprep_kernel<<<32, 256>>>(W);
    gemv_kernel<<<NT / 64, 256>>>(f, b);

    cudaFuncSetAttribute(assign_kernel,
                         cudaFuncAttributeMaxDynamicSharedMemorySize, SMEM_BYTES);
    assign_kernel<<<148, 1024, SMEM_BYTES>>>();

    epilogue_kernel<<<NT / 256, 256>>>(out);
}